// round 12
// baseline (speedup 1.0000x reference)
#include <cuda_runtime.h>
#include <cuda_fp16.h>
#include <cstdint>

#define N_NODES 100000
#define N_EDGES 1600000
#define HID 64
#define NGROUPS (N_EDGES / 32)       // 50000
#define NODE_GROUPS (N_NODES / 32)   // 3125

// ---------- device scratch ----------
__device__ float g_h[N_NODES * HID];
__device__ float g_agg[N_NODES * HID];
__device__ float g_P[N_NODES * HID];
__device__ float g_Q[N_NODES * HID];
__device__ float g_xA[N_NODES * 3];
__device__ float g_xB[N_NODES * 3];

// ---------- helpers ----------
__device__ __forceinline__ float silu(float v) {
    float u = 0.5f * v, th;
    asm("tanh.approx.f32 %0, %1;" : "=f"(th) : "f"(u));
    return v * fmaf(th, 0.5f, 0.5f);
}
__device__ __forceinline__ void red_add_v4(float* addr, float a, float b, float c, float d) {
    asm volatile("red.global.add.v4.f32 [%0], {%1, %2, %3, %4};"
                 :: "l"(addr), "f"(a), "f"(b), "f"(c), "f"(d) : "memory");
}
__device__ __forceinline__ uint32_t f16_pack2(float f0, float f1) {
    uint32_t h;
    asm("cvt.rn.f16x2.f32 %0, %1, %2;" : "=r"(h) : "f"(f1), "f"(f0));
    return h;
}
__device__ __forceinline__ void mma16816(float c[4], const uint32_t a[4],
                                         uint32_t b0, uint32_t b1) {
    asm volatile(
        "mma.sync.aligned.m16n8k16.row.col.f32.f16.f16.f32 "
        "{%0,%1,%2,%3}, {%4,%5,%6,%7}, {%8,%9}, {%0,%1,%2,%3};"
        : "+f"(c[0]), "+f"(c[1]), "+f"(c[2]), "+f"(c[3])
        : "r"(a[0]), "r"(a[1]), "r"(a[2]), "r"(a[3]), "r"(b0), "r"(b1));
}
// stage 64x64 fp32 weight (row-major [k][n]) as f16 B-tile [n][kk] u32 words, stride 36
__device__ __forceinline__ void stage_btile(uint32_t* dst,
                                            const float* __restrict__ W, int tid, int nth) {
    for (int i = tid; i < 2048; i += nth) {
        int n = i >> 5, kk = i & 31;
        dst[n * 36 + kk] = f16_pack2(W[(2 * kk) * 64 + n], W[(2 * kk + 1) * 64 + n]);
    }
}
// 1-term K=64 mma, A from smem
__device__ __forceinline__ void mma1_smem(float acc[16][4],
                                          const uint32_t* __restrict__ Ah,
                                          const uint32_t* __restrict__ Bh,
                                          int g, int t) {
    #pragma unroll
    for (int kt = 0; kt < 4; kt++) {
        uint32_t ah[2][4];
        #pragma unroll
        for (int mt = 0; mt < 2; mt++) {
            int rb = (16 * mt + g) * 36 + 8 * kt + t;
            ah[mt][0] = Ah[rb];     ah[mt][1] = Ah[rb + 8 * 36];
            ah[mt][2] = Ah[rb + 4]; ah[mt][3] = Ah[rb + 8 * 36 + 4];
        }
        #pragma unroll
        for (int nt = 0; nt < 8; nt++) {
            int bi = (8 * nt + g) * 36 + 8 * kt + t;
            uint32_t bh0 = Bh[bi], bh1 = Bh[bi + 4];
            #pragma unroll
            for (int mt = 0; mt < 2; mt++)
                mma16816(acc[mt * 8 + nt], ah[mt], bh0, bh1);
        }
    }
}
// 1-term K=64 mma, A from register fragments
__device__ __forceinline__ void mma1_reg(float acc[16][4],
                                         const uint32_t fh[2][4][4],
                                         const uint32_t* __restrict__ Bh,
                                         int g, int t) {
    #pragma unroll
    for (int kt = 0; kt < 4; kt++) {
        #pragma unroll
        for (int nt = 0; nt < 8; nt++) {
            int bi = (8 * nt + g) * 36 + 8 * kt + t;
            uint32_t bh0 = Bh[bi], bh1 = Bh[bi + 4];
            #pragma unroll
            for (int mt = 0; mt < 2; mt++)
                mma16816(acc[mt * 8 + nt], fh[mt][kt], bh0, bh1);
        }
    }
}

__global__ void dummy_kernel() {}

// ---------- fused init+pre: h = emb[z]+tmean, agg = 0, P = h@W1a+b1, Q = h@W1b ----------
#define IP_A   0
#define IP_B   2304
#define IP_B1  4608
#define IP_TM  4672
#define IP_WBASE 4736
#define IP_WW  1152
#define IP_SMEM_WORDS (IP_WBASE + 6 * IP_WW)
#define IP_SMEM_BYTES (IP_SMEM_WORDS * 4)

__global__ void __launch_bounds__(192)
initpre_kernel(const int* __restrict__ z, const float* __restrict__ emb,
               const float* __restrict__ t,
               const float* __restrict__ tw1, const float* __restrict__ tb1,
               const float* __restrict__ tw2, const float* __restrict__ tb2,
               int B,
               const float* __restrict__ ew1, const float* __restrict__ eb1g) {
    extern __shared__ uint32_t smw[];
    float* smf = (float*)smw;
    const int tid = threadIdx.x;

    stage_btile(smw + IP_A, ew1, tid, 192);
    stage_btile(smw + IP_B, ew1 + 64 * 64, tid, 192);
    if (tid < 64) smf[IP_B1 + tid] = eb1g[tid];
    __syncthreads();     // also covers s1 staging area reuse below? compute tmean via regs
    // compute tmean: thread j<64 computes tm[j]
    __shared__ float s1[64];
    if (tid < 64) {
        float w = tw1[tid], bb = tb1[tid];
        float acc = 0.f;
        for (int b = 0; b < B; b++) acc += silu(t[b] * w + bb);
        s1[tid] = acc / (float)B;
    }
    __syncthreads();
    if (tid < 64) {
        float o = tb2[tid];
        for (int k = 0; k < 64; k++) o += s1[k] * tw2[k * 64 + tid];
        smf[IP_TM + tid] = o;
    }
    __syncthreads();

    const int lane = tid & 31;
    const int wrp = tid >> 5;
    const int g = lane >> 2;
    const int t4 = lane & 3;
    uint32_t* Ah = smw + IP_WBASE + wrp * IP_WW;
    const float tm0 = smf[IP_TM + 2 * lane];
    const float tm1 = smf[IP_TM + 2 * lane + 1];

    const int gwarp = (blockIdx.x * 192 + tid) >> 5;
    const int nwarps = (gridDim.x * 192) >> 5;

    for (int grp = gwarp; grp < NODE_GROUPS; grp += nwarps) {
        const int base = grp * 32;
        const int zv = __ldg(&z[base + lane]);
        __syncwarp();
        #pragma unroll 4
        for (int e2 = 0; e2 < 32; e2++) {
            int nz = __shfl_sync(0xffffffffu, zv, e2);
            float2 ev = __ldg((const float2*)(emb + (size_t)nz * 64 + 2 * lane));
            float h0 = ev.x + tm0, h1 = ev.y + tm1;
            size_t idx = (size_t)(base + e2) * 64 + 2 * lane;
            *(float2*)(g_h + idx) = make_float2(h0, h1);
            *(float2*)(g_agg + idx) = make_float2(0.f, 0.f);
            Ah[e2 * 36 + lane] = f16_pack2(h0, h1);
        }
        __syncwarp();

        float accP[16][4], accQ[16][4];
        #pragma unroll
        for (int nt = 0; nt < 8; nt++) {
            float2 bb = *(const float2*)(smf + IP_B1 + 8 * nt + 2 * t4);
            #pragma unroll
            for (int mt = 0; mt < 2; mt++) {
                accP[mt * 8 + nt][0] = bb.x; accP[mt * 8 + nt][1] = bb.y;
                accP[mt * 8 + nt][2] = bb.x; accP[mt * 8 + nt][3] = bb.y;
                accQ[mt * 8 + nt][0] = 0.f; accQ[mt * 8 + nt][1] = 0.f;
                accQ[mt * 8 + nt][2] = 0.f; accQ[mt * 8 + nt][3] = 0.f;
            }
        }
        mma1_smem(accP, Ah, smw + IP_A, g, t4);
        mma1_smem(accQ, Ah, smw + IP_B, g, t4);
        #pragma unroll
        for (int mt = 0; mt < 2; mt++) {
            int r1 = base + 16 * mt + g;
            int r2 = r1 + 8;
            #pragma unroll
            for (int nt = 0; nt < 8; nt++) {
                int c = 8 * nt + 2 * t4;
                *(float2*)(g_P + (size_t)r1 * 64 + c) = make_float2(accP[mt * 8 + nt][0], accP[mt * 8 + nt][1]);
                *(float2*)(g_P + (size_t)r2 * 64 + c) = make_float2(accP[mt * 8 + nt][2], accP[mt * 8 + nt][3]);
                *(float2*)(g_Q + (size_t)r1 * 64 + c) = make_float2(accQ[mt * 8 + nt][0], accQ[mt * 8 + nt][1]);
                *(float2*)(g_Q + (size_t)r2 * 64 + c) = make_float2(accQ[mt * 8 + nt][2], accQ[mt * 8 + nt][3]);
            }
        }
    }
}

// ---------- edge kernel (fp16 1-term, 4 CTAs/SM) — unchanged from round 11 ----------
#define B_W2H  0
#define B_C1H  2304
#define SC_W1C 4608
#define SC_B2  4672
#define SC_CB1 4736
#define SC_CW2 4800
#define SC_CB2 4864
#define WARP_BASE 4868
#define WARP_W 1152
#define EDGE_SMEM_WORDS (WARP_BASE + 4 * WARP_W)
#define EDGE_SMEM_BYTES (EDGE_SMEM_WORDS * 4)   // 37,904 B -> 4 CTAs/SM

__global__ void __launch_bounds__(128, 4)
edge_kernel(const float* __restrict__ x, float* __restrict__ xn,
            const int* __restrict__ ei,
            const float* __restrict__ w1c_g,
            const float* __restrict__ ew2, const float* __restrict__ eb2g,
            const float* __restrict__ cw1, const float* __restrict__ cb1g,
            const float* __restrict__ cw2g, const float* __restrict__ cb2g,
            int do_agg) {
    extern __shared__ uint32_t smw[];
    float* smf = (float*)smw;
    const int tid = threadIdx.x;

    stage_btile(smw + B_W2H, ew2, tid, 128);
    stage_btile(smw + B_C1H, cw1, tid, 128);
    if (tid < 64) {
        smf[SC_W1C + tid] = w1c_g[tid];
        smf[SC_B2 + tid]  = eb2g[tid];
        smf[SC_CB1 + tid] = cb1g[tid];
        smf[SC_CW2 + tid] = cw2g[tid];
    }
    if (tid == 0) smf[SC_CB2] = cb2g[0];
    __syncthreads();

    const int lane = tid & 31;
    const int wrp = tid >> 5;
    const int g = lane >> 2;
    const int t = lane & 3;
    uint32_t* Ah = smw + WARP_BASE + wrp * WARP_W;
    const float w1c0 = smf[SC_W1C + 2 * lane];
    const float w1c1 = smf[SC_W1C + 2 * lane + 1];
    const float cb2s = smf[SC_CB2];

    const int gwarp = (blockIdx.x * 128 + tid) >> 5;
    const int nwarps = (gridDim.x * 128) >> 5;

    int grp = gwarp;
    int s_n = 0, d_n = 0;
    float xs0 = 0, xs1 = 0, xs2 = 0, xd0 = 0, xd1 = 0, xd2 = 0;
    if (grp < NGROUPS) {
        int e = grp * 32 + lane;
        s_n = ei[e]; d_n = ei[N_EDGES + e];
        xs0 = __ldg(&x[s_n * 3 + 0]); xs1 = __ldg(&x[s_n * 3 + 1]); xs2 = __ldg(&x[s_n * 3 + 2]);
        xd0 = __ldg(&x[d_n * 3 + 0]); xd1 = __ldg(&x[d_n * 3 + 1]); xd2 = __ldg(&x[d_n * 3 + 2]);
    }

    for (; grp < NGROUPS; grp += nwarps) {
        const int s = s_n, d = d_n;
        const float dx0 = xd0 - xs0;
        const float dx1 = xd1 - xs1;
        const float dx2 = xd2 - xs2;
        const float r2 = dx0 * dx0 + dx1 * dx1 + dx2 * dx2;

        __syncwarp();
        #pragma unroll 4
        for (int e2 = 0; e2 < 32; e2++) {
            int nd = __shfl_sync(0xffffffffu, d, e2);
            int ns = __shfl_sync(0xffffffffu, s, e2);
            float rr = __shfl_sync(0xffffffffu, r2, e2);
            float2 pv = __ldg((const float2*)(g_P + (size_t)nd * 64 + 2 * lane));
            float2 qv = __ldg((const float2*)(g_Q + (size_t)ns * 64 + 2 * lane));
            float f0 = silu(fmaf(rr, w1c0, pv.x + qv.x));
            float f1 = silu(fmaf(rr, w1c1, pv.y + qv.y));
            Ah[e2 * 36 + lane] = f16_pack2(f0, f1);
        }
        __syncwarp();

        {
            int gn = grp + nwarps;
            if (gn < NGROUPS) {
                int e = gn * 32 + lane;
                s_n = ei[e]; d_n = ei[N_EDGES + e];
                xs0 = __ldg(&x[s_n * 3 + 0]); xs1 = __ldg(&x[s_n * 3 + 1]); xs2 = __ldg(&x[s_n * 3 + 2]);
                xd0 = __ldg(&x[d_n * 3 + 0]); xd1 = __ldg(&x[d_n * 3 + 1]); xd2 = __ldg(&x[d_n * 3 + 2]);
            }
        }

        float acc[16][4];
        #pragma unroll
        for (int nt = 0; nt < 8; nt++) {
            float2 bb = *(const float2*)(smf + SC_B2 + 8 * nt + 2 * t);
            #pragma unroll
            for (int mt = 0; mt < 2; mt++) {
                acc[mt * 8 + nt][0] = bb.x; acc[mt * 8 + nt][1] = bb.y;
                acc[mt * 8 + nt][2] = bb.x; acc[mt * 8 + nt][3] = bb.y;
            }
        }
        mma1_smem(acc, Ah, smw + B_W2H, g, t);

        uint32_t mh[2][4][4];
        int dtop[2], dbot[2];
        #pragma unroll
        for (int mt = 0; mt < 2; mt++) {
            dtop[mt] = __shfl_sync(0xffffffffu, d, 16 * mt + g);
            dbot[mt] = __shfl_sync(0xffffffffu, d, 16 * mt + g + 8);
        }
        const int colbase_off = 2 * (t & ~1);
        #pragma unroll
        for (int mt = 0; mt < 2; mt++) {
            #pragma unroll
            for (int nt = 0; nt < 8; nt++) {
                float v0 = silu(acc[mt * 8 + nt][0]);
                float v1 = silu(acc[mt * 8 + nt][1]);
                float v2 = silu(acc[mt * 8 + nt][2]);
                float v3 = silu(acc[mt * 8 + nt][3]);
                if (do_agg) {
                    float px = (t & 1) ? v0 : v2;
                    float qx = (t & 1) ? v1 : v3;
                    float pr = __shfl_xor_sync(0xffffffffu, px, 1);
                    float qr = __shfl_xor_sync(0xffffffffu, qx, 1);
                    int row = (t & 1) ? dbot[mt] : dtop[mt];
                    int col = 8 * nt + colbase_off;
                    float a0 = (t & 1) ? pr : v0;
                    float a1 = (t & 1) ? qr : v1;
                    float a2 = (t & 1) ? v2 : pr;
                    float a3 = (t & 1) ? v3 : qr;
                    red_add_v4(&g_agg[(size_t)row * 64 + col], a0, a1, a2, a3);
                }
                int kt = nt >> 1, o = (nt & 1) * 2;
                mh[mt][kt][o]     = f16_pack2(v0, v1);
                mh[mt][kt][o + 1] = f16_pack2(v2, v3);
            }
        }

        float acc2[16][4];
        #pragma unroll
        for (int nt = 0; nt < 8; nt++) {
            float2 bb = *(const float2*)(smf + SC_CB1 + 8 * nt + 2 * t);
            #pragma unroll
            for (int mt = 0; mt < 2; mt++) {
                acc2[mt * 8 + nt][0] = bb.x; acc2[mt * 8 + nt][1] = bb.y;
                acc2[mt * 8 + nt][2] = bb.x; acc2[mt * 8 + nt][3] = bb.y;
            }
        }
        mma1_reg(acc2, mh, smw + B_C1H, g, t);

        float pr0 = 0.f, pr1 = 0.f, pr2 = 0.f, pr3 = 0.f;
        #pragma unroll
        for (int nt = 0; nt < 8; nt++) {
            float2 cwv = *(const float2*)(smf + SC_CW2 + 8 * nt + 2 * t);
            pr0 = fmaf(silu(acc2[nt][0]), cwv.x, pr0);
            pr0 = fmaf(silu(acc2[nt][1]), cwv.y, pr0);
            pr1 = fmaf(silu(acc2[nt][2]), cwv.x, pr1);
            pr1 = fmaf(silu(acc2[nt][3]), cwv.y, pr1);
            pr2 = fmaf(silu(acc2[8 + nt][0]), cwv.x, pr2);
            pr2 = fmaf(silu(acc2[8 + nt][1]), cwv.y, pr2);
            pr3 = fmaf(silu(acc2[8 + nt][2]), cwv.x, pr3);
            pr3 = fmaf(silu(acc2[8 + nt][3]), cwv.y, pr3);
        }
        pr0 += __shfl_xor_sync(0xffffffffu, pr0, 1);
        pr0 += __shfl_xor_sync(0xffffffffu, pr0, 2);
        pr1 += __shfl_xor_sync(0xffffffffu, pr1, 1);
        pr1 += __shfl_xor_sync(0xffffffffu, pr1, 2);
        pr2 += __shfl_xor_sync(0xffffffffu, pr2, 1);
        pr2 += __shfl_xor_sync(0xffffffffu, pr2, 2);
        pr3 += __shfl_xor_sync(0xffffffffu, pr3, 1);
        pr3 += __shfl_xor_sync(0xffffffffu, pr3, 2);
        float p = (t == 0) ? pr0 : (t == 1) ? pr1 : (t == 2) ? pr2 : pr3;
        const int e2l = g + 8 * t;
        p += cb2s;
        int dd = __shfl_sync(0xffffffffu, d, e2l);
        float ddx0 = __shfl_sync(0xffffffffu, dx0, e2l);
        float ddx1 = __shfl_sync(0xffffffffu, dx1, e2l);
        float ddx2 = __shfl_sync(0xffffffffu, dx2, e2l);
        atomicAdd(&xn[dd * 3 + 0], ddx0 * p);
        atomicAdd(&xn[dd * 3 + 1], ddx1 * p);
        atomicAdd(&xn[dd * 3 + 2], ddx2 * p);
    }
}

// ---------- node kernel: 448 thr, both gathers issued before mma ----------
#define N_W1H  0
#define N_W1A  2304
#define N_W2   4608
#define N_PA   6912
#define N_PB   9216
#define N_B1W  11520
#define N_B2W  11584
#define N_EB1W 11648
#define N_ABASE 11712
#define N_AW   2304          // two halves: h at +0, agg at +1152
#define NODE_SMEM_WORDS (N_ABASE + 14 * N_AW)
#define NODE_SMEM_BYTES (NODE_SMEM_WORDS * 4)   // 175,872 B -> 1 CTA/SM @ 448 thr

__global__ void __launch_bounds__(448)
node_kernel(const float* __restrict__ nw1, const float* __restrict__ nb1g,
            const float* __restrict__ nw2, const float* __restrict__ nb2g,
            const float* __restrict__ ew1n, const float* __restrict__ eb1n) {
    extern __shared__ uint32_t smw[];
    float* smf = (float*)smw;
    const int tid = threadIdx.x;

    stage_btile(smw + N_W1H, nw1, tid, 448);
    stage_btile(smw + N_W1A, nw1 + 64 * 64, tid, 448);
    stage_btile(smw + N_W2, nw2, tid, 448);
    stage_btile(smw + N_PA, ew1n, tid, 448);
    stage_btile(smw + N_PB, ew1n + 64 * 64, tid, 448);
    if (tid < 64) {
        smf[N_B1W + tid]  = nb1g[tid];
        smf[N_B2W + tid]  = nb2g[tid];
        smf[N_EB1W + tid] = eb1n[tid];
    }
    __syncthreads();

    const int lane = tid & 31;
    const int wrp = tid >> 5;
    const int g = lane >> 2;
    const int t = lane & 3;
    uint32_t* Ah = smw + N_ABASE + wrp * N_AW;
    uint32_t* Aa = Ah + 1152;

    const int gwarp = (blockIdx.x * 448 + tid) >> 5;
    const int nwarps = (gridDim.x * 448) >> 5;

    for (int grp = gwarp; grp < NODE_GROUPS; grp += nwarps) {
        const int base = grp * 32;

        // ---- gather h AND agg (zeroing agg) before any mma: overlapped latency ----
        __syncwarp();
        #pragma unroll 4
        for (int e2 = 0; e2 < 32; e2++) {
            size_t idx = (size_t)(base + e2) * 64 + 2 * lane;
            float2 hv = __ldg((const float2*)(g_h + idx));
            float2* ap = (float2*)(g_agg + idx);
            float2 av = *ap;
            *ap = make_float2(0.f, 0.f);
            Ah[e2 * 36 + lane] = f16_pack2(hv.x, hv.y);
            Aa[e2 * 36 + lane] = f16_pack2(av.x, av.y);
        }
        __syncwarp();

        float acc1[16][4];
        #pragma unroll
        for (int nt = 0; nt < 8; nt++) {
            float2 bb = *(const float2*)(smf + N_B1W + 8 * nt + 2 * t);
            #pragma unroll
            for (int mt = 0; mt < 2; mt++) {
                acc1[mt * 8 + nt][0] = bb.x; acc1[mt * 8 + nt][1] = bb.y;
                acc1[mt * 8 + nt][2] = bb.x; acc1[mt * 8 + nt][3] = bb.y;
            }
        }
        mma1_smem(acc1, Ah, smw + N_W1H, g, t);
        mma1_smem(acc1, Aa, smw + N_W1A, g, t);

        // ---- hid = silu(acc1) -> register A frags ----
        uint32_t mh[2][4][4];
        #pragma unroll
        for (int mt = 0; mt < 2; mt++) {
            #pragma unroll
            for (int nt = 0; nt < 8; nt++) {
                float v0 = silu(acc1[mt * 8 + nt][0]);
                float v1 = silu(acc1[mt * 8 + nt][1]);
                float v2 = silu(acc1[mt * 8 + nt][2]);
                float v3 = silu(acc1[mt * 8 + nt][3]);
                int kt = nt >> 1, o = (nt & 1) * 2;
                mh[mt][kt][o]     = f16_pack2(v0, v1);
                mh[mt][kt][o + 1] = f16_pack2(v2, v3);
            }
        }

        // ---- acc2 = hid @ W2 + b2; h_new = h_old + acc2 ----
        float acc2[16][4];
        #pragma unroll
        for (int nt = 0; nt < 8; nt++) {
            float2 bb = *(const float2*)(smf + N_B2W + 8 * nt + 2 * t);
            #pragma unroll
            for (int mt = 0; mt < 2; mt++) {
                acc2[mt * 8 + nt][0] = bb.x; acc2[mt * 8 + nt][1] = bb.y;
                acc2[mt * 8 + nt][2] = bb.x; acc2[mt * 8 + nt][3] = bb.y;
            }
        }
        mma1_reg(acc2, mh, smw + N_W2, g, t);

        uint32_t hh[2][4][4];
        #pragma unroll
        for (int mt = 0; mt < 2; mt++) {
            int r1 = base + 16 * mt + g;
            int r2 = r1 + 8;
            #pragma unroll
            for (int nt = 0; nt < 8; nt++) {
                int c = 8 * nt + 2 * t;
                float2 h1 = __ldg((const float2*)(g_h + (size_t)r1 * 64 + c));
                float2 h2 = __ldg((const float2*)(g_h + (size_t)r2 * 64 + c));
                float v0 = h1.x + acc2[mt * 8 + nt][0];
                float v1 = h1.y + acc2[mt * 8 + nt][1];
                float v2 = h2.x + acc2[mt * 8 + nt][2];
                float v3 = h2.y + acc2[mt * 8 + nt][3];
                *(float2*)(g_h + (size_t)r1 * 64 + c) = make_float2(v0, v1);
                *(float2*)(g_h + (size_t)r2 * 64 + c) = make_float2(v2, v3);
                int kt = nt >> 1, o = (nt & 1) * 2;
                hh[mt][kt][o]     = f16_pack2(v0, v1);
                hh[mt][kt][o + 1] = f16_pack2(v2, v3);
            }
        }

        // ---- P = h_new @ W1a' + b1' ----
        float accp[16][4];
        #pragma unroll
        for (int nt = 0; nt < 8; nt++) {
            float2 bb = *(const float2*)(smf + N_EB1W + 8 * nt + 2 * t);
            #pragma unroll
            for (int mt = 0; mt < 2; mt++) {
                accp[mt * 8 + nt][0] = bb.x; accp[mt * 8 + nt][1] = bb.y;
                accp[mt * 8 + nt][2] = bb.x; accp[mt * 8 + nt][3] = bb.y;
            }
        }
        mma1_reg(accp, hh, smw + N_PA, g, t);
        #pragma unroll
        for (int mt = 0; mt < 2; mt++) {
            int r1 = base + 16 * mt + g;
            int r2 = r1 + 8;
            #pragma unroll
            for (int nt = 0; nt < 8; nt++) {
                int c = 8 * nt + 2 * t;
                *(float2*)(g_P + (size_t)r1 * 64 + c) = make_float2(accp[mt * 8 + nt][0], accp[mt * 8 + nt][1]);
                *(float2*)(g_P + (size_t)r2 * 64 + c) = make_float2(accp[mt * 8 + nt][2], accp[mt * 8 + nt][3]);
            }
        }

        // ---- Q = h_new @ W1b' ----
        #pragma unroll
        for (int a = 0; a < 16; a++) {
            accp[a][0] = 0.f; accp[a][1] = 0.f; accp[a][2] = 0.f; accp[a][3] = 0.f;
        }
        mma1_reg(accp, hh, smw + N_PB, g, t);
        #pragma unroll
        for (int mt = 0; mt < 2; mt++) {
            int r1 = base + 16 * mt + g;
            int r2 = r1 + 8;
            #pragma unroll
            for (int nt = 0; nt < 8; nt++) {
                int c = 8 * nt + 2 * t;
                *(float2*)(g_Q + (size_t)r1 * 64 + c) = make_float2(accp[mt * 8 + nt][0], accp[mt * 8 + nt][1]);
                *(float2*)(g_Q + (size_t)r2 * 64 + c) = make_float2(accp[mt * 8 + nt][2], accp[mt * 8 + nt][3]);
            }
        }
    }
}

// ---------- launch ----------
extern "C" void kernel_launch(void* const* d_in, const int* in_sizes, int n_in,
                              void* d_out, int out_size) {
    const float* x   = (const float*)d_in[0];
    const int*   z   = (const int*)d_in[1];
    const float* t   = (const float*)d_in[2];
    const int*   ei  = (const int*)d_in[3];
    const float* emb = (const float*)d_in[4];
    const float* tw1 = (const float*)d_in[5];
    const float* tb1 = (const float*)d_in[6];
    const float* tw2 = (const float*)d_in[7];
    const float* tb2 = (const float*)d_in[8];
    const float* ew1 = (const float*)d_in[9];
    const float* eb1 = (const float*)d_in[10];
    const float* ew2 = (const float*)d_in[11];
    const float* eb2 = (const float*)d_in[12];
    const float* cw1 = (const float*)d_in[13];
    const float* cb1 = (const float*)d_in[14];
    const float* cw2 = (const float*)d_in[15];
    const float* cb2 = (const float*)d_in[16];
    const float* nw1 = (const float*)d_in[17];
    const float* nb1 = (const float*)d_in[18];
    const float* nw2 = (const float*)d_in[19];
    const float* nb2 = (const float*)d_in[20];
    float* out = (float*)d_out;
    const int B = in_sizes[2];

    float *pxA, *pxB;
    cudaGetSymbolAddress((void**)&pxA, g_xA);
    cudaGetSymbolAddress((void**)&pxB, g_xB);

    cudaFuncSetAttribute(edge_kernel, cudaFuncAttributeMaxDynamicSharedMemorySize, EDGE_SMEM_BYTES);
    cudaFuncSetAttribute(node_kernel, cudaFuncAttributeMaxDynamicSharedMemorySize, NODE_SMEM_BYTES);
    cudaFuncSetAttribute(initpre_kernel, cudaFuncAttributeMaxDynamicSharedMemorySize, IP_SMEM_BYTES);

    const size_t XB = (size_t)N_NODES * 3 * sizeof(float);
    const int EGRID = 608;

    // launches: 0 initpre, 1 edge0, 2 node0, 3 dummy, 4 dummy, 5 edge1 (ncu -s 5 target)
    initpre_kernel<<<304, 192, IP_SMEM_BYTES>>>(z, emb, t, tw1, tb1, tw2, tb2, B,
                                                ew1 + 0 * 129 * 64, eb1 + 0 * 64);

    // ---- layer 0 ----
    cudaMemcpyAsync(pxB, x, XB, cudaMemcpyDeviceToDevice, 0);
    edge_kernel<<<EGRID, 128, EDGE_SMEM_BYTES>>>(x, pxB, ei,
        ew1 + 0 * 129 * 64 + 128 * 64, ew2 + 0 * 4096, eb2 + 0 * 64,
        cw1 + 0 * 4096, cb1 + 0 * 64, cw2 + 0 * 64, cb2 + 0, 1);
    node_kernel<<<152, 448, NODE_SMEM_BYTES>>>(nw1 + 0 * 128 * 64, nb1 + 0 * 64,
                                               nw2 + 0 * 4096, nb2 + 0 * 64,
                                               ew1 + 1 * 129 * 64, eb1 + 1 * 64);
    dummy_kernel<<<1, 32>>>();
    dummy_kernel<<<1, 32>>>();

    // ---- layer 1 ----
    cudaMemcpyAsync(pxA, pxB, XB, cudaMemcpyDeviceToDevice, 0);
    edge_kernel<<<EGRID, 128, EDGE_SMEM_BYTES>>>(pxB, pxA, ei,
        ew1 + 1 * 129 * 64 + 128 * 64, ew2 + 1 * 4096, eb2 + 1 * 64,
        cw1 + 1 * 4096, cb1 + 1 * 64, cw2 + 1 * 64, cb2 + 1, 1);
    node_kernel<<<152, 448, NODE_SMEM_BYTES>>>(nw1 + 1 * 128 * 64, nb1 + 1 * 64,
                                               nw2 + 1 * 4096, nb2 + 1 * 64,
                                               ew1 + 2 * 129 * 64, eb1 + 2 * 64);

    // ---- layer 2: agg/node dead, write x' straight to d_out ----
    cudaMemcpyAsync(out, pxA, XB, cudaMemcpyDeviceToDevice, 0);
    edge_kernel<<<EGRID, 128, EDGE_SMEM_BYTES>>>(pxA, out, ei,
        ew1 + 2 * 129 * 64 + 128 * 64, ew2 + 2 * 4096, eb2 + 2 * 64,
        cw1 + 2 * 4096, cb1 + 2 * 64, cw2 + 2 * 64, cb2 + 2, 0);
}

// round 13
// speedup vs baseline: 1.3030x; 1.3030x over previous
#include <cuda_runtime.h>
#include <cuda_fp16.h>
#include <cstdint>

#define N_NODES 100000
#define N_EDGES 1600000
#define HID 64
#define NGROUPS (N_EDGES / 32)       // 50000
#define NODE_GROUPS (N_NODES / 32)   // 3125

// ---------- device scratch ----------
__device__ float g_h[N_NODES * HID];
__device__ float g_agg[N_NODES * HID];
__device__ float g_P[N_NODES * HID];
__device__ float g_Q[N_NODES * HID];
__device__ float g_xA[N_NODES * 3];
__device__ float g_xB[N_NODES * 3];

// ---------- helpers ----------
__device__ __forceinline__ float silu(float v) {
    float u = 0.5f * v, th;
    asm("tanh.approx.f32 %0, %1;" : "=f"(th) : "f"(u));
    return v * fmaf(th, 0.5f, 0.5f);
}
__device__ __forceinline__ void red_add_v4(float* addr, float a, float b, float c, float d) {
    asm volatile("red.global.add.v4.f32 [%0], {%1, %2, %3, %4};"
                 :: "l"(addr), "f"(a), "f"(b), "f"(c), "f"(d) : "memory");
}
__device__ __forceinline__ uint32_t f16_pack2(float f0, float f1) {
    uint32_t h;
    asm("cvt.rn.f16x2.f32 %0, %1, %2;" : "=r"(h) : "f"(f1), "f"(f0));
    return h;
}
__device__ __forceinline__ void mma16816(float c[4], const uint32_t a[4],
                                         uint32_t b0, uint32_t b1) {
    asm volatile(
        "mma.sync.aligned.m16n8k16.row.col.f32.f16.f16.f32 "
        "{%0,%1,%2,%3}, {%4,%5,%6,%7}, {%8,%9}, {%0,%1,%2,%3};"
        : "+f"(c[0]), "+f"(c[1]), "+f"(c[2]), "+f"(c[3])
        : "r"(a[0]), "r"(a[1]), "r"(a[2]), "r"(a[3]), "r"(b0), "r"(b1));
}
// stage 64x64 fp32 weight (row-major [k][n]) as f16 B-tile [n][kk] u32 words, stride 36
__device__ __forceinline__ void stage_btile(uint32_t* dst,
                                            const float* __restrict__ W, int tid, int nth) {
    for (int i = tid; i < 2048; i += nth) {
        int n = i >> 5, kk = i & 31;
        dst[n * 36 + kk] = f16_pack2(W[(2 * kk) * 64 + n], W[(2 * kk + 1) * 64 + n]);
    }
}
// 1-term K=64 mma, A from smem
__device__ __forceinline__ void mma1_smem(float acc[16][4],
                                          const uint32_t* __restrict__ Ah,
                                          const uint32_t* __restrict__ Bh,
                                          int g, int t) {
    #pragma unroll
    for (int kt = 0; kt < 4; kt++) {
        uint32_t ah[2][4];
        #pragma unroll
        for (int mt = 0; mt < 2; mt++) {
            int rb = (16 * mt + g) * 36 + 8 * kt + t;
            ah[mt][0] = Ah[rb];     ah[mt][1] = Ah[rb + 8 * 36];
            ah[mt][2] = Ah[rb + 4]; ah[mt][3] = Ah[rb + 8 * 36 + 4];
        }
        #pragma unroll
        for (int nt = 0; nt < 8; nt++) {
            int bi = (8 * nt + g) * 36 + 8 * kt + t;
            uint32_t bh0 = Bh[bi], bh1 = Bh[bi + 4];
            #pragma unroll
            for (int mt = 0; mt < 2; mt++)
                mma16816(acc[mt * 8 + nt], ah[mt], bh0, bh1);
        }
    }
}
// 1-term K=64 mma, A from register fragments
__device__ __forceinline__ void mma1_reg(float acc[16][4],
                                         const uint32_t fh[2][4][4],
                                         const uint32_t* __restrict__ Bh,
                                         int g, int t) {
    #pragma unroll
    for (int kt = 0; kt < 4; kt++) {
        #pragma unroll
        for (int nt = 0; nt < 8; nt++) {
            int bi = (8 * nt + g) * 36 + 8 * kt + t;
            uint32_t bh0 = Bh[bi], bh1 = Bh[bi + 4];
            #pragma unroll
            for (int mt = 0; mt < 2; mt++)
                mma16816(acc[mt * 8 + nt], fh[mt][kt], bh0, bh1);
        }
    }
}

// ---------- init ----------
__global__ void init_kernel(const int* __restrict__ z, const float* __restrict__ emb,
                            const float* __restrict__ t,
                            const float* __restrict__ tw1, const float* __restrict__ tb1,
                            const float* __restrict__ tw2, const float* __restrict__ tb2,
                            int B) {
    __shared__ float s1[HID];
    __shared__ float tm[HID];
    int tidb = threadIdx.x;
    if (tidb < HID) {
        float w = tw1[tidb], bb = tb1[tidb];
        float acc = 0.f;
        for (int b = 0; b < B; b++) acc += silu(t[b] * w + bb);
        s1[tidb] = acc / (float)B;
    }
    __syncthreads();
    if (tidb < HID) {
        float o = tb2[tidb];
        for (int k = 0; k < HID; k++) o += s1[k] * tw2[k * HID + tidb];
        tm[tidb] = o;
    }
    __syncthreads();
    int i = blockIdx.x * blockDim.x + tidb;
    if (i < N_NODES * HID) {
        int node = i >> 6, j = i & 63;
        g_h[i] = emb[z[node] * HID + j] + tm[j];
        g_agg[i] = 0.f;
    }
}

__global__ void dummy_kernel() {}

// ---------- pre kernel (layer 0 only): P = h@W1a + b1, Q = h@W1b ----------
#define PW_A  0
#define PW_B  2304
#define P_B1W 4608
#define P_WBASE 4672
#define P_WW 1152
#define P_SMEM_WORDS (P_WBASE + 6 * P_WW)
#define P_SMEM_BYTES (P_SMEM_WORDS * 4)   // 46,336 B

__global__ void __launch_bounds__(192)
pre_kernel(const float* __restrict__ ew1, const float* __restrict__ eb1g) {
    extern __shared__ uint32_t smw[];
    float* smf = (float*)smw;
    const int tid = threadIdx.x;

    stage_btile(smw + PW_A, ew1, tid, 192);
    stage_btile(smw + PW_B, ew1 + 64 * 64, tid, 192);
    if (tid < 64) smf[P_B1W + tid] = eb1g[tid];
    __syncthreads();

    const int lane = tid & 31;
    const int wrp = tid >> 5;
    const int g = lane >> 2;
    const int t = lane & 3;
    uint32_t* Ah = smw + P_WBASE + wrp * P_WW;

    const int gwarp = (blockIdx.x * 192 + tid) >> 5;
    const int nwarps = (gridDim.x * 192) >> 5;

    for (int grp = gwarp; grp < NODE_GROUPS; grp += nwarps) {
        const int base = grp * 32;
        __syncwarp();
        // full unroll: all 32 loads in flight (MLP ~32)
        #pragma unroll
        for (int e2 = 0; e2 < 32; e2++) {
            float2 hv = __ldg((const float2*)(g_h + (size_t)(base + e2) * 64 + 2 * lane));
            Ah[e2 * 36 + lane] = f16_pack2(hv.x, hv.y);
        }
        __syncwarp();

        float accP[16][4], accQ[16][4];
        #pragma unroll
        for (int nt = 0; nt < 8; nt++) {
            float2 bb = *(const float2*)(smf + P_B1W + 8 * nt + 2 * t);
            #pragma unroll
            for (int mt = 0; mt < 2; mt++) {
                accP[mt * 8 + nt][0] = bb.x; accP[mt * 8 + nt][1] = bb.y;
                accP[mt * 8 + nt][2] = bb.x; accP[mt * 8 + nt][3] = bb.y;
                accQ[mt * 8 + nt][0] = 0.f; accQ[mt * 8 + nt][1] = 0.f;
                accQ[mt * 8 + nt][2] = 0.f; accQ[mt * 8 + nt][3] = 0.f;
            }
        }
        mma1_smem(accP, Ah, smw + PW_A, g, t);
        mma1_smem(accQ, Ah, smw + PW_B, g, t);
        #pragma unroll
        for (int mt = 0; mt < 2; mt++) {
            int r1 = base + 16 * mt + g;
            int r2 = r1 + 8;
            #pragma unroll
            for (int nt = 0; nt < 8; nt++) {
                int c = 8 * nt + 2 * t;
                *(float2*)(g_P + (size_t)r1 * 64 + c) = make_float2(accP[mt * 8 + nt][0], accP[mt * 8 + nt][1]);
                *(float2*)(g_P + (size_t)r2 * 64 + c) = make_float2(accP[mt * 8 + nt][2], accP[mt * 8 + nt][3]);
                *(float2*)(g_Q + (size_t)r1 * 64 + c) = make_float2(accQ[mt * 8 + nt][0], accQ[mt * 8 + nt][1]);
                *(float2*)(g_Q + (size_t)r2 * 64 + c) = make_float2(accQ[mt * 8 + nt][2], accQ[mt * 8 + nt][3]);
            }
        }
    }
}

// ---------- edge kernel (fp16 1-term, 4 CTAs/SM) ----------
#define B_W2H  0
#define B_C1H  2304
#define SC_W1C 4608
#define SC_B2  4672
#define SC_CB1 4736
#define SC_CW2 4800
#define SC_CB2 4864
#define WARP_BASE 4868
#define WARP_W 1152
#define EDGE_SMEM_WORDS (WARP_BASE + 4 * WARP_W)
#define EDGE_SMEM_BYTES (EDGE_SMEM_WORDS * 4)   // 37,904 B -> 4 CTAs/SM

__global__ void __launch_bounds__(128, 4)
edge_kernel(const float* __restrict__ x, float* __restrict__ xn,
            const int* __restrict__ ei,
            const float* __restrict__ w1c_g,
            const float* __restrict__ ew2, const float* __restrict__ eb2g,
            const float* __restrict__ cw1, const float* __restrict__ cb1g,
            const float* __restrict__ cw2g, const float* __restrict__ cb2g,
            int do_agg) {
    extern __shared__ uint32_t smw[];
    float* smf = (float*)smw;
    const int tid = threadIdx.x;

    stage_btile(smw + B_W2H, ew2, tid, 128);
    stage_btile(smw + B_C1H, cw1, tid, 128);
    if (tid < 64) {
        smf[SC_W1C + tid] = w1c_g[tid];
        smf[SC_B2 + tid]  = eb2g[tid];
        smf[SC_CB1 + tid] = cb1g[tid];
        smf[SC_CW2 + tid] = cw2g[tid];
    }
    if (tid == 0) smf[SC_CB2] = cb2g[0];
    __syncthreads();

    const int lane = tid & 31;
    const int wrp = tid >> 5;
    const int g = lane >> 2;
    const int t = lane & 3;
    uint32_t* Ah = smw + WARP_BASE + wrp * WARP_W;
    const float w1c0 = smf[SC_W1C + 2 * lane];
    const float w1c1 = smf[SC_W1C + 2 * lane + 1];
    const float cb2s = smf[SC_CB2];

    const int gwarp = (blockIdx.x * 128 + tid) >> 5;
    const int nwarps = (gridDim.x * 128) >> 5;

    int grp = gwarp;
    int s_n = 0, d_n = 0;
    float xs0 = 0, xs1 = 0, xs2 = 0, xd0 = 0, xd1 = 0, xd2 = 0;
    if (grp < NGROUPS) {
        int e = grp * 32 + lane;
        s_n = ei[e]; d_n = ei[N_EDGES + e];
        xs0 = __ldg(&x[s_n * 3 + 0]); xs1 = __ldg(&x[s_n * 3 + 1]); xs2 = __ldg(&x[s_n * 3 + 2]);
        xd0 = __ldg(&x[d_n * 3 + 0]); xd1 = __ldg(&x[d_n * 3 + 1]); xd2 = __ldg(&x[d_n * 3 + 2]);
    }

    for (; grp < NGROUPS; grp += nwarps) {
        const int s = s_n, d = d_n;
        const float dx0 = xd0 - xs0;
        const float dx1 = xd1 - xs1;
        const float dx2 = xd2 - xs2;
        const float r2 = dx0 * dx0 + dx1 * dx1 + dx2 * dx2;

        // ---- gather + phase1 fused (indices via shfl); unroll 8 for MLP 16 ----
        __syncwarp();
        #pragma unroll 8
        for (int e2 = 0; e2 < 32; e2++) {
            int nd = __shfl_sync(0xffffffffu, d, e2);
            int ns = __shfl_sync(0xffffffffu, s, e2);
            float rr = __shfl_sync(0xffffffffu, r2, e2);
            float2 pv = __ldg((const float2*)(g_P + (size_t)nd * 64 + 2 * lane));
            float2 qv = __ldg((const float2*)(g_Q + (size_t)ns * 64 + 2 * lane));
            float f0 = silu(fmaf(rr, w1c0, pv.x + qv.x));
            float f1 = silu(fmaf(rr, w1c1, pv.y + qv.y));
            Ah[e2 * 36 + lane] = f16_pack2(f0, f1);
        }
        __syncwarp();

        // ---- prefetch next group ----
        {
            int gn = grp + nwarps;
            if (gn < NGROUPS) {
                int e = gn * 32 + lane;
                s_n = ei[e]; d_n = ei[N_EDGES + e];
                xs0 = __ldg(&x[s_n * 3 + 0]); xs1 = __ldg(&x[s_n * 3 + 1]); xs2 = __ldg(&x[s_n * 3 + 2]);
                xd0 = __ldg(&x[d_n * 3 + 0]); xd1 = __ldg(&x[d_n * 3 + 1]); xd2 = __ldg(&x[d_n * 3 + 2]);
            }
        }

        // ---- matmul1: D = ef1 @ W2 + b2 ----
        float acc[16][4];
        #pragma unroll
        for (int nt = 0; nt < 8; nt++) {
            float2 bb = *(const float2*)(smf + SC_B2 + 8 * nt + 2 * t);
            #pragma unroll
            for (int mt = 0; mt < 2; mt++) {
                acc[mt * 8 + nt][0] = bb.x; acc[mt * 8 + nt][1] = bb.y;
                acc[mt * 8 + nt][2] = bb.x; acc[mt * 8 + nt][3] = bb.y;
            }
        }
        mma1_smem(acc, Ah, smw + B_W2H, g, t);

        // ---- m = silu(D); paired red.v4; pack to matmul2 A frags ----
        uint32_t mh[2][4][4];
        int dtop[2], dbot[2];
        #pragma unroll
        for (int mt = 0; mt < 2; mt++) {
            dtop[mt] = __shfl_sync(0xffffffffu, d, 16 * mt + g);
            dbot[mt] = __shfl_sync(0xffffffffu, d, 16 * mt + g + 8);
        }
        const int colbase_off = 2 * (t & ~1);
        #pragma unroll
        for (int mt = 0; mt < 2; mt++) {
            #pragma unroll
            for (int nt = 0; nt < 8; nt++) {
                float v0 = silu(acc[mt * 8 + nt][0]);
                float v1 = silu(acc[mt * 8 + nt][1]);
                float v2 = silu(acc[mt * 8 + nt][2]);
                float v3 = silu(acc[mt * 8 + nt][3]);
                if (do_agg) {
                    float px = (t & 1) ? v0 : v2;
                    float qx = (t & 1) ? v1 : v3;
                    float pr = __shfl_xor_sync(0xffffffffu, px, 1);
                    float qr = __shfl_xor_sync(0xffffffffu, qx, 1);
                    int row = (t & 1) ? dbot[mt] : dtop[mt];
                    int col = 8 * nt + colbase_off;
                    float a0 = (t & 1) ? pr : v0;
                    float a1 = (t & 1) ? qr : v1;
                    float a2 = (t & 1) ? v2 : pr;
                    float a3 = (t & 1) ? v3 : qr;
                    red_add_v4(&g_agg[(size_t)row * 64 + col], a0, a1, a2, a3);
                }
                int kt = nt >> 1, o = (nt & 1) * 2;
                mh[mt][kt][o]     = f16_pack2(v0, v1);
                mh[mt][kt][o + 1] = f16_pack2(v2, v3);
            }
        }

        // ---- matmul2: D2 = m @ C1 + cb1 ----
        float acc2[16][4];
        #pragma unroll
        for (int nt = 0; nt < 8; nt++) {
            float2 bb = *(const float2*)(smf + SC_CB1 + 8 * nt + 2 * t);
            #pragma unroll
            for (int mt = 0; mt < 2; mt++) {
                acc2[mt * 8 + nt][0] = bb.x; acc2[mt * 8 + nt][1] = bb.y;
                acc2[mt * 8 + nt][2] = bb.x; acc2[mt * 8 + nt][3] = bb.y;
            }
        }
        mma1_reg(acc2, mh, smw + B_C1H, g, t);

        // ---- coord epilogue ----
        float pr0 = 0.f, pr1 = 0.f, pr2 = 0.f, pr3 = 0.f;
        #pragma unroll
        for (int nt = 0; nt < 8; nt++) {
            float2 cwv = *(const float2*)(smf + SC_CW2 + 8 * nt + 2 * t);
            pr0 = fmaf(silu(acc2[nt][0]), cwv.x, pr0);
            pr0 = fmaf(silu(acc2[nt][1]), cwv.y, pr0);
            pr1 = fmaf(silu(acc2[nt][2]), cwv.x, pr1);
            pr1 = fmaf(silu(acc2[nt][3]), cwv.y, pr1);
            pr2 = fmaf(silu(acc2[8 + nt][0]), cwv.x, pr2);
            pr2 = fmaf(silu(acc2[8 + nt][1]), cwv.y, pr2);
            pr3 = fmaf(silu(acc2[8 + nt][2]), cwv.x, pr3);
            pr3 = fmaf(silu(acc2[8 + nt][3]), cwv.y, pr3);
        }
        pr0 += __shfl_xor_sync(0xffffffffu, pr0, 1);
        pr0 += __shfl_xor_sync(0xffffffffu, pr0, 2);
        pr1 += __shfl_xor_sync(0xffffffffu, pr1, 1);
        pr1 += __shfl_xor_sync(0xffffffffu, pr1, 2);
        pr2 += __shfl_xor_sync(0xffffffffu, pr2, 1);
        pr2 += __shfl_xor_sync(0xffffffffu, pr2, 2);
        pr3 += __shfl_xor_sync(0xffffffffu, pr3, 1);
        pr3 += __shfl_xor_sync(0xffffffffu, pr3, 2);
        float p = (t == 0) ? pr0 : (t == 1) ? pr1 : (t == 2) ? pr2 : pr3;
        const int e2l = g + 8 * t;
        p += cb2s;
        int dd = __shfl_sync(0xffffffffu, d, e2l);
        float ddx0 = __shfl_sync(0xffffffffu, dx0, e2l);
        float ddx1 = __shfl_sync(0xffffffffu, dx1, e2l);
        float ddx2 = __shfl_sync(0xffffffffu, dx2, e2l);
        atomicAdd(&xn[dd * 3 + 0], ddx0 * p);
        atomicAdd(&xn[dd * 3 + 1], ddx1 * p);
        atomicAdd(&xn[dd * 3 + 2], ddx2 * p);
    }
}

// ---------- node kernel (fp16 1-term) + fused next-layer P/Q ----------
#define N_W1H  0
#define N_W1A  2304
#define N_W2   4608
#define N_PA   6912
#define N_PB   9216
#define N_B1W  11520
#define N_B2W  11584
#define N_EB1W 11648
#define N_ABASE 11712
#define N_AW   1152
#define NODE_SMEM_WORDS (N_ABASE + 12 * N_AW)
#define NODE_SMEM_BYTES (NODE_SMEM_WORDS * 4)   // 102,144 B -> 1 CTA/SM at 384 thr

__global__ void __launch_bounds__(384)
node_kernel(const float* __restrict__ nw1, const float* __restrict__ nb1g,
            const float* __restrict__ nw2, const float* __restrict__ nb2g,
            const float* __restrict__ ew1n, const float* __restrict__ eb1n) {
    extern __shared__ uint32_t smw[];
    float* smf = (float*)smw;
    const int tid = threadIdx.x;

    stage_btile(smw + N_W1H, nw1, tid, 384);
    stage_btile(smw + N_W1A, nw1 + 64 * 64, tid, 384);
    stage_btile(smw + N_W2, nw2, tid, 384);
    stage_btile(smw + N_PA, ew1n, tid, 384);
    stage_btile(smw + N_PB, ew1n + 64 * 64, tid, 384);
    if (tid < 64) {
        smf[N_B1W + tid]  = nb1g[tid];
        smf[N_B2W + tid]  = nb2g[tid];
        smf[N_EB1W + tid] = eb1n[tid];
    }
    __syncthreads();

    const int lane = tid & 31;
    const int wrp = tid >> 5;
    const int g = lane >> 2;
    const int t = lane & 3;
    uint32_t* Ah = smw + N_ABASE + wrp * N_AW;

    const int gwarp = (blockIdx.x * 384 + tid) >> 5;
    const int nwarps = (gridDim.x * 384) >> 5;

    for (int grp = gwarp; grp < NODE_GROUPS; grp += nwarps) {
        const int base = grp * 32;

        // ---- gather h -> A frags (full unroll: MLP ~32) ----
        __syncwarp();
        #pragma unroll
        for (int e2 = 0; e2 < 32; e2++) {
            float2 hv = __ldg((const float2*)(g_h + (size_t)(base + e2) * 64 + 2 * lane));
            Ah[e2 * 36 + lane] = f16_pack2(hv.x, hv.y);
        }
        __syncwarp();

        float acc1[16][4];
        #pragma unroll
        for (int nt = 0; nt < 8; nt++) {
            float2 bb = *(const float2*)(smf + N_B1W + 8 * nt + 2 * t);
            #pragma unroll
            for (int mt = 0; mt < 2; mt++) {
                acc1[mt * 8 + nt][0] = bb.x; acc1[mt * 8 + nt][1] = bb.y;
                acc1[mt * 8 + nt][2] = bb.x; acc1[mt * 8 + nt][3] = bb.y;
            }
        }
        mma1_smem(acc1, Ah, smw + N_W1H, g, t);

        // ---- gather agg (and zero it) full unroll; accumulate @ W1agg ----
        __syncwarp();
        #pragma unroll
        for (int e2 = 0; e2 < 32; e2++) {
            float2* ap = (float2*)(g_agg + (size_t)(base + e2) * 64 + 2 * lane);
            float2 av = *ap;
            *ap = make_float2(0.f, 0.f);
            Ah[e2 * 36 + lane] = f16_pack2(av.x, av.y);
        }
        __syncwarp();
        mma1_smem(acc1, Ah, smw + N_W1A, g, t);

        // ---- hid = silu(acc1) -> register A frags ----
        uint32_t mh[2][4][4];
        #pragma unroll
        for (int mt = 0; mt < 2; mt++) {
            #pragma unroll
            for (int nt = 0; nt < 8; nt++) {
                float v0 = silu(acc1[mt * 8 + nt][0]);
                float v1 = silu(acc1[mt * 8 + nt][1]);
                float v2 = silu(acc1[mt * 8 + nt][2]);
                float v3 = silu(acc1[mt * 8 + nt][3]);
                int kt = nt >> 1, o = (nt & 1) * 2;
                mh[mt][kt][o]     = f16_pack2(v0, v1);
                mh[mt][kt][o + 1] = f16_pack2(v2, v3);
            }
        }

        // ---- acc2 = hid @ W2 + b2; h_new = h_old + acc2 ----
        float acc2[16][4];
        #pragma unroll
        for (int nt = 0; nt < 8; nt++) {
            float2 bb = *(const float2*)(smf + N_B2W + 8 * nt + 2 * t);
            #pragma unroll
            for (int mt = 0; mt < 2; mt++) {
                acc2[mt * 8 + nt][0] = bb.x; acc2[mt * 8 + nt][1] = bb.y;
                acc2[mt * 8 + nt][2] = bb.x; acc2[mt * 8 + nt][3] = bb.y;
            }
        }
        mma1_reg(acc2, mh, smw + N_W2, g, t);

        // residual + writeback + pack h_new frags
        uint32_t hh[2][4][4];
        #pragma unroll
        for (int mt = 0; mt < 2; mt++) {
            int r1 = base + 16 * mt + g;
            int r2 = r1 + 8;
            #pragma unroll
            for (int nt = 0; nt < 8; nt++) {
                int c = 8 * nt + 2 * t;
                float2 h1 = __ldg((const float2*)(g_h + (size_t)r1 * 64 + c));
                float2 h2 = __ldg((const float2*)(g_h + (size_t)r2 * 64 + c));
                float v0 = h1.x + acc2[mt * 8 + nt][0];
                float v1 = h1.y + acc2[mt * 8 + nt][1];
                float v2 = h2.x + acc2[mt * 8 + nt][2];
                float v3 = h2.y + acc2[mt * 8 + nt][3];
                *(float2*)(g_h + (size_t)r1 * 64 + c) = make_float2(v0, v1);
                *(float2*)(g_h + (size_t)r2 * 64 + c) = make_float2(v2, v3);
                int kt = nt >> 1, o = (nt & 1) * 2;
                hh[mt][kt][o]     = f16_pack2(v0, v1);
                hh[mt][kt][o + 1] = f16_pack2(v2, v3);
            }
        }

        // ---- P = h_new @ W1a' + b1' ----
        float accp[16][4];
        #pragma unroll
        for (int nt = 0; nt < 8; nt++) {
            float2 bb = *(const float2*)(smf + N_EB1W + 8 * nt + 2 * t);
            #pragma unroll
            for (int mt = 0; mt < 2; mt++) {
                accp[mt * 8 + nt][0] = bb.x; accp[mt * 8 + nt][1] = bb.y;
                accp[mt * 8 + nt][2] = bb.x; accp[mt * 8 + nt][3] = bb.y;
            }
        }
        mma1_reg(accp, hh, smw + N_PA, g, t);
        #pragma unroll
        for (int mt = 0; mt < 2; mt++) {
            int r1 = base + 16 * mt + g;
            int r2 = r1 + 8;
            #pragma unroll
            for (int nt = 0; nt < 8; nt++) {
                int c = 8 * nt + 2 * t;
                *(float2*)(g_P + (size_t)r1 * 64 + c) = make_float2(accp[mt * 8 + nt][0], accp[mt * 8 + nt][1]);
                *(float2*)(g_P + (size_t)r2 * 64 + c) = make_float2(accp[mt * 8 + nt][2], accp[mt * 8 + nt][3]);
            }
        }

        // ---- Q = h_new @ W1b' ----
        #pragma unroll
        for (int a = 0; a < 16; a++) {
            accp[a][0] = 0.f; accp[a][1] = 0.f; accp[a][2] = 0.f; accp[a][3] = 0.f;
        }
        mma1_reg(accp, hh, smw + N_PB, g, t);
        #pragma unroll
        for (int mt = 0; mt < 2; mt++) {
            int r1 = base + 16 * mt + g;
            int r2 = r1 + 8;
            #pragma unroll
            for (int nt = 0; nt < 8; nt++) {
                int c = 8 * nt + 2 * t;
                *(float2*)(g_Q + (size_t)r1 * 64 + c) = make_float2(accp[mt * 8 + nt][0], accp[mt * 8 + nt][1]);
                *(float2*)(g_Q + (size_t)r2 * 64 + c) = make_float2(accp[mt * 8 + nt][2], accp[mt * 8 + nt][3]);
            }
        }
    }
}

// ---------- launch ----------
extern "C" void kernel_launch(void* const* d_in, const int* in_sizes, int n_in,
                              void* d_out, int out_size) {
    const float* x   = (const float*)d_in[0];
    const int*   z   = (const int*)d_in[1];
    const float* t   = (const float*)d_in[2];
    const int*   ei  = (const int*)d_in[3];
    const float* emb = (const float*)d_in[4];
    const float* tw1 = (const float*)d_in[5];
    const float* tb1 = (const float*)d_in[6];
    const float* tw2 = (const float*)d_in[7];
    const float* tb2 = (const float*)d_in[8];
    const float* ew1 = (const float*)d_in[9];
    const float* eb1 = (const float*)d_in[10];
    const float* ew2 = (const float*)d_in[11];
    const float* eb2 = (const float*)d_in[12];
    const float* cw1 = (const float*)d_in[13];
    const float* cb1 = (const float*)d_in[14];
    const float* cw2 = (const float*)d_in[15];
    const float* cb2 = (const float*)d_in[16];
    const float* nw1 = (const float*)d_in[17];
    const float* nb1 = (const float*)d_in[18];
    const float* nw2 = (const float*)d_in[19];
    const float* nb2 = (const float*)d_in[20];
    float* out = (float*)d_out;
    const int B = in_sizes[2];

    float *pxA, *pxB;
    cudaGetSymbolAddress((void**)&pxA, g_xA);
    cudaGetSymbolAddress((void**)&pxB, g_xB);

    cudaFuncSetAttribute(edge_kernel, cudaFuncAttributeMaxDynamicSharedMemorySize, EDGE_SMEM_BYTES);
    cudaFuncSetAttribute(node_kernel, cudaFuncAttributeMaxDynamicSharedMemorySize, NODE_SMEM_BYTES);
    cudaFuncSetAttribute(pre_kernel,  cudaFuncAttributeMaxDynamicSharedMemorySize, P_SMEM_BYTES);

    const size_t XB = (size_t)N_NODES * 3 * sizeof(float);
    const int EGRID = 608;   // 4 CTAs/SM x 152

    // launches: 0 init, 1 pre, 2 edge0, 3 node0, 4 dummy, 5 edge1 (ncu -s 5 target)
    init_kernel<<<(N_NODES * HID + 255) / 256, 256>>>(z, emb, t, tw1, tb1, tw2, tb2, B);

    // ---- layer 0 ----
    pre_kernel<<<304, 192, P_SMEM_BYTES>>>(ew1 + 0 * 129 * 64, eb1 + 0 * 64);
    cudaMemcpyAsync(pxB, x, XB, cudaMemcpyDeviceToDevice, 0);
    edge_kernel<<<EGRID, 128, EDGE_SMEM_BYTES>>>(x, pxB, ei,
        ew1 + 0 * 129 * 64 + 128 * 64, ew2 + 0 * 4096, eb2 + 0 * 64,
        cw1 + 0 * 4096, cb1 + 0 * 64, cw2 + 0 * 64, cb2 + 0, 1);
    node_kernel<<<152, 384, NODE_SMEM_BYTES>>>(nw1 + 0 * 128 * 64, nb1 + 0 * 64,
                                               nw2 + 0 * 4096, nb2 + 0 * 64,
                                               ew1 + 1 * 129 * 64, eb1 + 1 * 64);
    dummy_kernel<<<1, 32>>>();

    // ---- layer 1 ----
    cudaMemcpyAsync(pxA, pxB, XB, cudaMemcpyDeviceToDevice, 0);
    edge_kernel<<<EGRID, 128, EDGE_SMEM_BYTES>>>(pxB, pxA, ei,
        ew1 + 1 * 129 * 64 + 128 * 64, ew2 + 1 * 4096, eb2 + 1 * 64,
        cw1 + 1 * 4096, cb1 + 1 * 64, cw2 + 1 * 64, cb2 + 1, 1);
    node_kernel<<<152, 384, NODE_SMEM_BYTES>>>(nw1 + 1 * 128 * 64, nb1 + 1 * 64,
                                               nw2 + 1 * 4096, nb2 + 1 * 64,
                                               ew1 + 2 * 129 * 64, eb1 + 2 * 64);

    // ---- layer 2: agg/node dead, write x' straight to d_out ----
    cudaMemcpyAsync(out, pxA, XB, cudaMemcpyDeviceToDevice, 0);
    edge_kernel<<<EGRID, 128, EDGE_SMEM_BYTES>>>(pxA, out, ei,
        ew1 + 2 * 129 * 64 + 128 * 64, ew2 + 2 * 4096, eb2 + 2 * 64,
        cw1 + 2 * 4096, cb1 + 2 * 64, cw2 + 2 * 64, cb2 + 2, 0);
}

// round 14
// speedup vs baseline: 1.3242x; 1.0163x over previous
#include <cuda_runtime.h>
#include <cuda_fp16.h>
#include <cstdint>

#define N_NODES 100000
#define N_EDGES 1600000
#define HID 64
#define NGROUPS (N_EDGES / 32)       // 50000
#define NODE_GROUPS (N_NODES / 32)   // 3125

// ---------- device scratch ----------
__device__ float g_h[N_NODES * HID];
__device__ float g_agg[N_NODES * HID];
__device__ float g_P[N_NODES * HID];
__device__ float g_Q[N_NODES * HID];
__device__ float g_xA[N_NODES * 3];
__device__ float g_xB[N_NODES * 3];

// ---------- helpers ----------
__device__ __forceinline__ float silu(float v) {
    float u = 0.5f * v, th;
    asm("tanh.approx.f32 %0, %1;" : "=f"(th) : "f"(u));
    return v * fmaf(th, 0.5f, 0.5f);
}
__device__ __forceinline__ void red_add_v4(float* addr, float a, float b, float c, float d) {
    asm volatile("red.global.add.v4.f32 [%0], {%1, %2, %3, %4};"
                 :: "l"(addr), "f"(a), "f"(b), "f"(c), "f"(d) : "memory");
}
__device__ __forceinline__ uint32_t f16_pack2(float f0, float f1) {
    uint32_t h;
    asm("cvt.rn.f16x2.f32 %0, %1, %2;" : "=r"(h) : "f"(f1), "f"(f0));
    return h;
}
__device__ __forceinline__ void mma16816(float c[4], const uint32_t a[4],
                                         uint32_t b0, uint32_t b1) {
    asm volatile(
        "mma.sync.aligned.m16n8k16.row.col.f32.f16.f16.f32 "
        "{%0,%1,%2,%3}, {%4,%5,%6,%7}, {%8,%9}, {%0,%1,%2,%3};"
        : "+f"(c[0]), "+f"(c[1]), "+f"(c[2]), "+f"(c[3])
        : "r"(a[0]), "r"(a[1]), "r"(a[2]), "r"(a[3]), "r"(b0), "r"(b1));
}
// stage 64x64 fp32 weight (row-major [k][n]) as f16 B-tile [n][kk] u32 words, stride 36
__device__ __forceinline__ void stage_btile(uint32_t* dst,
                                            const float* __restrict__ W, int tid, int nth) {
    for (int i = tid; i < 2048; i += nth) {
        int n = i >> 5, kk = i & 31;
        dst[n * 36 + kk] = f16_pack2(W[(2 * kk) * 64 + n], W[(2 * kk + 1) * 64 + n]);
    }
}
// 1-term K=64 mma, A from smem
__device__ __forceinline__ void mma1_smem(float acc[16][4],
                                          const uint32_t* __restrict__ Ah,
                                          const uint32_t* __restrict__ Bh,
                                          int g, int t) {
    #pragma unroll
    for (int kt = 0; kt < 4; kt++) {
        uint32_t ah[2][4];
        #pragma unroll
        for (int mt = 0; mt < 2; mt++) {
            int rb = (16 * mt + g) * 36 + 8 * kt + t;
            ah[mt][0] = Ah[rb];     ah[mt][1] = Ah[rb + 8 * 36];
            ah[mt][2] = Ah[rb + 4]; ah[mt][3] = Ah[rb + 8 * 36 + 4];
        }
        #pragma unroll
        for (int nt = 0; nt < 8; nt++) {
            int bi = (8 * nt + g) * 36 + 8 * kt + t;
            uint32_t bh0 = Bh[bi], bh1 = Bh[bi + 4];
            #pragma unroll
            for (int mt = 0; mt < 2; mt++)
                mma16816(acc[mt * 8 + nt], ah[mt], bh0, bh1);
        }
    }
}
// 1-term K=64 mma, A from register fragments
__device__ __forceinline__ void mma1_reg(float acc[16][4],
                                         const uint32_t fh[2][4][4],
                                         const uint32_t* __restrict__ Bh,
                                         int g, int t) {
    #pragma unroll
    for (int kt = 0; kt < 4; kt++) {
        #pragma unroll
        for (int nt = 0; nt < 8; nt++) {
            int bi = (8 * nt + g) * 36 + 8 * kt + t;
            uint32_t bh0 = Bh[bi], bh1 = Bh[bi + 4];
            #pragma unroll
            for (int mt = 0; mt < 2; mt++)
                mma16816(acc[mt * 8 + nt], fh[mt][kt], bh0, bh1);
        }
    }
}

// ---------- init ----------
__global__ void init_kernel(const int* __restrict__ z, const float* __restrict__ emb,
                            const float* __restrict__ t,
                            const float* __restrict__ tw1, const float* __restrict__ tb1,
                            const float* __restrict__ tw2, const float* __restrict__ tb2,
                            int B) {
    __shared__ float s1[HID];
    __shared__ float tm[HID];
    int tidb = threadIdx.x;
    if (tidb < HID) {
        float w = tw1[tidb], bb = tb1[tidb];
        float acc = 0.f;
        for (int b = 0; b < B; b++) acc += silu(t[b] * w + bb);
        s1[tidb] = acc / (float)B;
    }
    __syncthreads();
    if (tidb < HID) {
        float o = tb2[tidb];
        for (int k = 0; k < HID; k++) o += s1[k] * tw2[k * HID + tidb];
        tm[tidb] = o;
    }
    __syncthreads();
    int i = blockIdx.x * blockDim.x + tidb;
    if (i < N_NODES * HID) {
        int node = i >> 6, j = i & 63;
        g_h[i] = emb[z[node] * HID + j] + tm[j];
        g_agg[i] = 0.f;
    }
}

__global__ void dummy_kernel() {}

// ---------- pre kernel (layer 0 only): P = h@W1a + b1, Q = h@W1b ----------
#define PW_A  0
#define PW_B  2304
#define P_B1W 4608
#define P_WBASE 4672
#define P_WW 1152
#define P_SMEM_WORDS (P_WBASE + 6 * P_WW)
#define P_SMEM_BYTES (P_SMEM_WORDS * 4)   // 46,336 B

__global__ void __launch_bounds__(192)
pre_kernel(const float* __restrict__ ew1, const float* __restrict__ eb1g) {
    extern __shared__ uint32_t smw[];
    float* smf = (float*)smw;
    const int tid = threadIdx.x;

    stage_btile(smw + PW_A, ew1, tid, 192);
    stage_btile(smw + PW_B, ew1 + 64 * 64, tid, 192);
    if (tid < 64) smf[P_B1W + tid] = eb1g[tid];
    __syncthreads();

    const int lane = tid & 31;
    const int wrp = tid >> 5;
    const int g = lane >> 2;
    const int t = lane & 3;
    uint32_t* Ah = smw + P_WBASE + wrp * P_WW;

    const int gwarp = (blockIdx.x * 192 + tid) >> 5;
    const int nwarps = (gridDim.x * 192) >> 5;

    for (int grp = gwarp; grp < NODE_GROUPS; grp += nwarps) {
        const int base = grp * 32;
        __syncwarp();
        #pragma unroll
        for (int e2 = 0; e2 < 32; e2++) {
            float2 hv = __ldg((const float2*)(g_h + (size_t)(base + e2) * 64 + 2 * lane));
            Ah[e2 * 36 + lane] = f16_pack2(hv.x, hv.y);
        }
        __syncwarp();

        float accP[16][4], accQ[16][4];
        #pragma unroll
        for (int nt = 0; nt < 8; nt++) {
            float2 bb = *(const float2*)(smf + P_B1W + 8 * nt + 2 * t);
            #pragma unroll
            for (int mt = 0; mt < 2; mt++) {
                accP[mt * 8 + nt][0] = bb.x; accP[mt * 8 + nt][1] = bb.y;
                accP[mt * 8 + nt][2] = bb.x; accP[mt * 8 + nt][3] = bb.y;
                accQ[mt * 8 + nt][0] = 0.f; accQ[mt * 8 + nt][1] = 0.f;
                accQ[mt * 8 + nt][2] = 0.f; accQ[mt * 8 + nt][3] = 0.f;
            }
        }
        mma1_smem(accP, Ah, smw + PW_A, g, t);
        mma1_smem(accQ, Ah, smw + PW_B, g, t);
        #pragma unroll
        for (int mt = 0; mt < 2; mt++) {
            int r1 = base + 16 * mt + g;
            int r2 = r1 + 8;
            #pragma unroll
            for (int nt = 0; nt < 8; nt++) {
                int c = 8 * nt + 2 * t;
                *(float2*)(g_P + (size_t)r1 * 64 + c) = make_float2(accP[mt * 8 + nt][0], accP[mt * 8 + nt][1]);
                *(float2*)(g_P + (size_t)r2 * 64 + c) = make_float2(accP[mt * 8 + nt][2], accP[mt * 8 + nt][3]);
                *(float2*)(g_Q + (size_t)r1 * 64 + c) = make_float2(accQ[mt * 8 + nt][0], accQ[mt * 8 + nt][1]);
                *(float2*)(g_Q + (size_t)r2 * 64 + c) = make_float2(accQ[mt * 8 + nt][2], accQ[mt * 8 + nt][3]);
            }
        }
    }
}

// ---------- edge kernel (fp16 1-term, 4 CTAs/SM) ----------
#define B_W2H  0
#define B_C1H  2304
#define SC_W1C 4608
#define SC_B2  4672
#define SC_CB1 4736
#define SC_CW2 4800
#define SC_CB2 4864
#define WARP_BASE 4868
#define WARP_W 1152
#define EDGE_SMEM_WORDS (WARP_BASE + 4 * WARP_W)
#define EDGE_SMEM_BYTES (EDGE_SMEM_WORDS * 4)   // 37,904 B -> 4 CTAs/SM

__global__ void __launch_bounds__(128, 4)
edge_kernel(const float* __restrict__ x, float* __restrict__ xn,
            const int* __restrict__ ei,
            const float* __restrict__ w1c_g,
            const float* __restrict__ ew2, const float* __restrict__ eb2g,
            const float* __restrict__ cw1, const float* __restrict__ cb1g,
            const float* __restrict__ cw2g, const float* __restrict__ cb2g,
            int do_agg) {
    extern __shared__ uint32_t smw[];
    float* smf = (float*)smw;
    const int tid = threadIdx.x;

    stage_btile(smw + B_W2H, ew2, tid, 128);
    stage_btile(smw + B_C1H, cw1, tid, 128);
    if (tid < 64) {
        smf[SC_W1C + tid] = w1c_g[tid];
        smf[SC_B2 + tid]  = eb2g[tid];
        smf[SC_CB1 + tid] = cb1g[tid];
        smf[SC_CW2 + tid] = cw2g[tid];
    }
    if (tid == 0) smf[SC_CB2] = cb2g[0];
    __syncthreads();

    const int lane = tid & 31;
    const int wrp = tid >> 5;
    const int g = lane >> 2;
    const int t = lane & 3;
    uint32_t* Ah = smw + WARP_BASE + wrp * WARP_W;
    const float w1c0 = smf[SC_W1C + 2 * lane];
    const float w1c1 = smf[SC_W1C + 2 * lane + 1];
    const float cb2s = smf[SC_CB2];

    const int gwarp = (blockIdx.x * 128 + tid) >> 5;
    const int nwarps = (gridDim.x * 128) >> 5;

    int grp = gwarp;
    int s_n = 0, d_n = 0;
    float xs0 = 0, xs1 = 0, xs2 = 0, xd0 = 0, xd1 = 0, xd2 = 0;
    if (grp < NGROUPS) {
        int e = grp * 32 + lane;
        s_n = ei[e]; d_n = ei[N_EDGES + e];
        xs0 = __ldg(&x[s_n * 3 + 0]); xs1 = __ldg(&x[s_n * 3 + 1]); xs2 = __ldg(&x[s_n * 3 + 2]);
        xd0 = __ldg(&x[d_n * 3 + 0]); xd1 = __ldg(&x[d_n * 3 + 1]); xd2 = __ldg(&x[d_n * 3 + 2]);
    }

    for (; grp < NGROUPS; grp += nwarps) {
        const int s = s_n, d = d_n;
        const float dx0 = xd0 - xs0;
        const float dx1 = xd1 - xs1;
        const float dx2 = xd2 - xs2;
        const float r2 = dx0 * dx0 + dx1 * dx1 + dx2 * dx2;

        // ---- gather + phase1 fused (indices via shfl); unroll 16 -> ~32 loads in flight ----
        __syncwarp();
        #pragma unroll 16
        for (int e2 = 0; e2 < 32; e2++) {
            int nd = __shfl_sync(0xffffffffu, d, e2);
            int ns = __shfl_sync(0xffffffffu, s, e2);
            float rr = __shfl_sync(0xffffffffu, r2, e2);
            float2 pv = __ldg((const float2*)(g_P + (size_t)nd * 64 + 2 * lane));
            float2 qv = __ldg((const float2*)(g_Q + (size_t)ns * 64 + 2 * lane));
            float f0 = silu(fmaf(rr, w1c0, pv.x + qv.x));
            float f1 = silu(fmaf(rr, w1c1, pv.y + qv.y));
            Ah[e2 * 36 + lane] = f16_pack2(f0, f1);
        }
        __syncwarp();

        // ---- prefetch next group ----
        {
            int gn = grp + nwarps;
            if (gn < NGROUPS) {
                int e = gn * 32 + lane;
                s_n = ei[e]; d_n = ei[N_EDGES + e];
                xs0 = __ldg(&x[s_n * 3 + 0]); xs1 = __ldg(&x[s_n * 3 + 1]); xs2 = __ldg(&x[s_n * 3 + 2]);
                xd0 = __ldg(&x[d_n * 3 + 0]); xd1 = __ldg(&x[d_n * 3 + 1]); xd2 = __ldg(&x[d_n * 3 + 2]);
            }
        }

        // ---- matmul1: D = ef1 @ W2 + b2 ----
        float acc[16][4];
        #pragma unroll
        for (int nt = 0; nt < 8; nt++) {
            float2 bb = *(const float2*)(smf + SC_B2 + 8 * nt + 2 * t);
            #pragma unroll
            for (int mt = 0; mt < 2; mt++) {
                acc[mt * 8 + nt][0] = bb.x; acc[mt * 8 + nt][1] = bb.y;
                acc[mt * 8 + nt][2] = bb.x; acc[mt * 8 + nt][3] = bb.y;
            }
        }
        mma1_smem(acc, Ah, smw + B_W2H, g, t);

        // ---- m = silu(D); paired red.v4; pack to matmul2 A frags ----
        uint32_t mh[2][4][4];
        int dtop[2], dbot[2];
        #pragma unroll
        for (int mt = 0; mt < 2; mt++) {
            dtop[mt] = __shfl_sync(0xffffffffu, d, 16 * mt + g);
            dbot[mt] = __shfl_sync(0xffffffffu, d, 16 * mt + g + 8);
        }
        const int colbase_off = 2 * (t & ~1);
        #pragma unroll
        for (int mt = 0; mt < 2; mt++) {
            #pragma unroll
            for (int nt = 0; nt < 8; nt++) {
                float v0 = silu(acc[mt * 8 + nt][0]);
                float v1 = silu(acc[mt * 8 + nt][1]);
                float v2 = silu(acc[mt * 8 + nt][2]);
                float v3 = silu(acc[mt * 8 + nt][3]);
                if (do_agg) {
                    float px = (t & 1) ? v0 : v2;
                    float qx = (t & 1) ? v1 : v3;
                    float pr = __shfl_xor_sync(0xffffffffu, px, 1);
                    float qr = __shfl_xor_sync(0xffffffffu, qx, 1);
                    int row = (t & 1) ? dbot[mt] : dtop[mt];
                    int col = 8 * nt + colbase_off;
                    float a0 = (t & 1) ? pr : v0;
                    float a1 = (t & 1) ? qr : v1;
                    float a2 = (t & 1) ? v2 : pr;
                    float a3 = (t & 1) ? v3 : qr;
                    red_add_v4(&g_agg[(size_t)row * 64 + col], a0, a1, a2, a3);
                }
                int kt = nt >> 1, o = (nt & 1) * 2;
                mh[mt][kt][o]     = f16_pack2(v0, v1);
                mh[mt][kt][o + 1] = f16_pack2(v2, v3);
            }
        }

        // ---- matmul2: D2 = m @ C1 + cb1 ----
        float acc2[16][4];
        #pragma unroll
        for (int nt = 0; nt < 8; nt++) {
            float2 bb = *(const float2*)(smf + SC_CB1 + 8 * nt + 2 * t);
            #pragma unroll
            for (int mt = 0; mt < 2; mt++) {
                acc2[mt * 8 + nt][0] = bb.x; acc2[mt * 8 + nt][1] = bb.y;
                acc2[mt * 8 + nt][2] = bb.x; acc2[mt * 8 + nt][3] = bb.y;
            }
        }
        mma1_reg(acc2, mh, smw + B_C1H, g, t);

        // ---- coord epilogue ----
        float pr0 = 0.f, pr1 = 0.f, pr2 = 0.f, pr3 = 0.f;
        #pragma unroll
        for (int nt = 0; nt < 8; nt++) {
            float2 cwv = *(const float2*)(smf + SC_CW2 + 8 * nt + 2 * t);
            pr0 = fmaf(silu(acc2[nt][0]), cwv.x, pr0);
            pr0 = fmaf(silu(acc2[nt][1]), cwv.y, pr0);
            pr1 = fmaf(silu(acc2[nt][2]), cwv.x, pr1);
            pr1 = fmaf(silu(acc2[nt][3]), cwv.y, pr1);
            pr2 = fmaf(silu(acc2[8 + nt][0]), cwv.x, pr2);
            pr2 = fmaf(silu(acc2[8 + nt][1]), cwv.y, pr2);
            pr3 = fmaf(silu(acc2[8 + nt][2]), cwv.x, pr3);
            pr3 = fmaf(silu(acc2[8 + nt][3]), cwv.y, pr3);
        }
        pr0 += __shfl_xor_sync(0xffffffffu, pr0, 1);
        pr0 += __shfl_xor_sync(0xffffffffu, pr0, 2);
        pr1 += __shfl_xor_sync(0xffffffffu, pr1, 1);
        pr1 += __shfl_xor_sync(0xffffffffu, pr1, 2);
        pr2 += __shfl_xor_sync(0xffffffffu, pr2, 1);
        pr2 += __shfl_xor_sync(0xffffffffu, pr2, 2);
        pr3 += __shfl_xor_sync(0xffffffffu, pr3, 1);
        pr3 += __shfl_xor_sync(0xffffffffu, pr3, 2);
        float p = (t == 0) ? pr0 : (t == 1) ? pr1 : (t == 2) ? pr2 : pr3;
        const int e2l = g + 8 * t;
        p += cb2s;
        int dd = __shfl_sync(0xffffffffu, d, e2l);
        float ddx0 = __shfl_sync(0xffffffffu, dx0, e2l);
        float ddx1 = __shfl_sync(0xffffffffu, dx1, e2l);
        float ddx2 = __shfl_sync(0xffffffffu, dx2, e2l);
        atomicAdd(&xn[dd * 3 + 0], ddx0 * p);
        atomicAdd(&xn[dd * 3 + 1], ddx1 * p);
        atomicAdd(&xn[dd * 3 + 2], ddx2 * p);
    }
}

// ---------- node kernel (fp16 1-term) + fused next-layer P/Q ----------
#define N_W1H  0
#define N_W1A  2304
#define N_W2   4608
#define N_PA   6912
#define N_PB   9216
#define N_B1W  11520
#define N_B2W  11584
#define N_EB1W 11648
#define N_ABASE 11712
#define N_AW   1152
#define NODE_SMEM_WORDS (N_ABASE + 12 * N_AW)
#define NODE_SMEM_BYTES (NODE_SMEM_WORDS * 4)   // 102,144 B -> 1 CTA/SM at 384 thr

__global__ void __launch_bounds__(384)
node_kernel(const float* __restrict__ nw1, const float* __restrict__ nb1g,
            const float* __restrict__ nw2, const float* __restrict__ nb2g,
            const float* __restrict__ ew1n, const float* __restrict__ eb1n) {
    extern __shared__ uint32_t smw[];
    float* smf = (float*)smw;
    const int tid = threadIdx.x;

    stage_btile(smw + N_W1H, nw1, tid, 384);
    stage_btile(smw + N_W1A, nw1 + 64 * 64, tid, 384);
    stage_btile(smw + N_W2, nw2, tid, 384);
    stage_btile(smw + N_PA, ew1n, tid, 384);
    stage_btile(smw + N_PB, ew1n + 64 * 64, tid, 384);
    if (tid < 64) {
        smf[N_B1W + tid]  = nb1g[tid];
        smf[N_B2W + tid]  = nb2g[tid];
        smf[N_EB1W + tid] = eb1n[tid];
    }
    __syncthreads();

    const int lane = tid & 31;
    const int wrp = tid >> 5;
    const int g = lane >> 2;
    const int t = lane & 3;
    uint32_t* Ah = smw + N_ABASE + wrp * N_AW;

    const int gwarp = (blockIdx.x * 384 + tid) >> 5;
    const int nwarps = (gridDim.x * 384) >> 5;

    for (int grp = gwarp; grp < NODE_GROUPS; grp += nwarps) {
        const int base = grp * 32;

        __syncwarp();
        #pragma unroll
        for (int e2 = 0; e2 < 32; e2++) {
            float2 hv = __ldg((const float2*)(g_h + (size_t)(base + e2) * 64 + 2 * lane));
            Ah[e2 * 36 + lane] = f16_pack2(hv.x, hv.y);
        }
        __syncwarp();

        float acc1[16][4];
        #pragma unroll
        for (int nt = 0; nt < 8; nt++) {
            float2 bb = *(const float2*)(smf + N_B1W + 8 * nt + 2 * t);
            #pragma unroll
            for (int mt = 0; mt < 2; mt++) {
                acc1[mt * 8 + nt][0] = bb.x; acc1[mt * 8 + nt][1] = bb.y;
                acc1[mt * 8 + nt][2] = bb.x; acc1[mt * 8 + nt][3] = bb.y;
            }
        }
        mma1_smem(acc1, Ah, smw + N_W1H, g, t);

        __syncwarp();
        #pragma unroll
        for (int e2 = 0; e2 < 32; e2++) {
            float2* ap = (float2*)(g_agg + (size_t)(base + e2) * 64 + 2 * lane);
            float2 av = *ap;
            *ap = make_float2(0.f, 0.f);
            Ah[e2 * 36 + lane] = f16_pack2(av.x, av.y);
        }
        __syncwarp();
        mma1_smem(acc1, Ah, smw + N_W1A, g, t);

        uint32_t mh[2][4][4];
        #pragma unroll
        for (int mt = 0; mt < 2; mt++) {
            #pragma unroll
            for (int nt = 0; nt < 8; nt++) {
                float v0 = silu(acc1[mt * 8 + nt][0]);
                float v1 = silu(acc1[mt * 8 + nt][1]);
                float v2 = silu(acc1[mt * 8 + nt][2]);
                float v3 = silu(acc1[mt * 8 + nt][3]);
                int kt = nt >> 1, o = (nt & 1) * 2;
                mh[mt][kt][o]     = f16_pack2(v0, v1);
                mh[mt][kt][o + 1] = f16_pack2(v2, v3);
            }
        }

        float acc2[16][4];
        #pragma unroll
        for (int nt = 0; nt < 8; nt++) {
            float2 bb = *(const float2*)(smf + N_B2W + 8 * nt + 2 * t);
            #pragma unroll
            for (int mt = 0; mt < 2; mt++) {
                acc2[mt * 8 + nt][0] = bb.x; acc2[mt * 8 + nt][1] = bb.y;
                acc2[mt * 8 + nt][2] = bb.x; acc2[mt * 8 + nt][3] = bb.y;
            }
        }
        mma1_reg(acc2, mh, smw + N_W2, g, t);

        uint32_t hh[2][4][4];
        #pragma unroll
        for (int mt = 0; mt < 2; mt++) {
            int r1 = base + 16 * mt + g;
            int r2 = r1 + 8;
            #pragma unroll
            for (int nt = 0; nt < 8; nt++) {
                int c = 8 * nt + 2 * t;
                float2 h1 = __ldg((const float2*)(g_h + (size_t)r1 * 64 + c));
                float2 h2 = __ldg((const float2*)(g_h + (size_t)r2 * 64 + c));
                float v0 = h1.x + acc2[mt * 8 + nt][0];
                float v1 = h1.y + acc2[mt * 8 + nt][1];
                float v2 = h2.x + acc2[mt * 8 + nt][2];
                float v3 = h2.y + acc2[mt * 8 + nt][3];
                *(float2*)(g_h + (size_t)r1 * 64 + c) = make_float2(v0, v1);
                *(float2*)(g_h + (size_t)r2 * 64 + c) = make_float2(v2, v3);
                int kt = nt >> 1, o = (nt & 1) * 2;
                hh[mt][kt][o]     = f16_pack2(v0, v1);
                hh[mt][kt][o + 1] = f16_pack2(v2, v3);
            }
        }

        float accp[16][4];
        #pragma unroll
        for (int nt = 0; nt < 8; nt++) {
            float2 bb = *(const float2*)(smf + N_EB1W + 8 * nt + 2 * t);
            #pragma unroll
            for (int mt = 0; mt < 2; mt++) {
                accp[mt * 8 + nt][0] = bb.x; accp[mt * 8 + nt][1] = bb.y;
                accp[mt * 8 + nt][2] = bb.x; accp[mt * 8 + nt][3] = bb.y;
            }
        }
        mma1_reg(accp, hh, smw + N_PA, g, t);
        #pragma unroll
        for (int mt = 0; mt < 2; mt++) {
            int r1 = base + 16 * mt + g;
            int r2 = r1 + 8;
            #pragma unroll
            for (int nt = 0; nt < 8; nt++) {
                int c = 8 * nt + 2 * t;
                *(float2*)(g_P + (size_t)r1 * 64 + c) = make_float2(accp[mt * 8 + nt][0], accp[mt * 8 + nt][1]);
                *(float2*)(g_P + (size_t)r2 * 64 + c) = make_float2(accp[mt * 8 + nt][2], accp[mt * 8 + nt][3]);
            }
        }

        #pragma unroll
        for (int a = 0; a < 16; a++) {
            accp[a][0] = 0.f; accp[a][1] = 0.f; accp[a][2] = 0.f; accp[a][3] = 0.f;
        }
        mma1_reg(accp, hh, smw + N_PB, g, t);
        #pragma unroll
        for (int mt = 0; mt < 2; mt++) {
            int r1 = base + 16 * mt + g;
            int r2 = r1 + 8;
            #pragma unroll
            for (int nt = 0; nt < 8; nt++) {
                int c = 8 * nt + 2 * t;
                *(float2*)(g_Q + (size_t)r1 * 64 + c) = make_float2(accp[mt * 8 + nt][0], accp[mt * 8 + nt][1]);
                *(float2*)(g_Q + (size_t)r2 * 64 + c) = make_float2(accp[mt * 8 + nt][2], accp[mt * 8 + nt][3]);
            }
        }
    }
}

// ---------- launch ----------
extern "C" void kernel_launch(void* const* d_in, const int* in_sizes, int n_in,
                              void* d_out, int out_size) {
    const float* x   = (const float*)d_in[0];
    const int*   z   = (const int*)d_in[1];
    const float* t   = (const float*)d_in[2];
    const int*   ei  = (const int*)d_in[3];
    const float* emb = (const float*)d_in[4];
    const float* tw1 = (const float*)d_in[5];
    const float* tb1 = (const float*)d_in[6];
    const float* tw2 = (const float*)d_in[7];
    const float* tb2 = (const float*)d_in[8];
    const float* ew1 = (const float*)d_in[9];
    const float* eb1 = (const float*)d_in[10];
    const float* ew2 = (const float*)d_in[11];
    const float* eb2 = (const float*)d_in[12];
    const float* cw1 = (const float*)d_in[13];
    const float* cb1 = (const float*)d_in[14];
    const float* cw2 = (const float*)d_in[15];
    const float* cb2 = (const float*)d_in[16];
    const float* nw1 = (const float*)d_in[17];
    const float* nb1 = (const float*)d_in[18];
    const float* nw2 = (const float*)d_in[19];
    const float* nb2 = (const float*)d_in[20];
    float* out = (float*)d_out;
    const int B = in_sizes[2];

    float *pxA, *pxB;
    cudaGetSymbolAddress((void**)&pxA, g_xA);
    cudaGetSymbolAddress((void**)&pxB, g_xB);

    cudaFuncSetAttribute(edge_kernel, cudaFuncAttributeMaxDynamicSharedMemorySize, EDGE_SMEM_BYTES);
    cudaFuncSetAttribute(node_kernel, cudaFuncAttributeMaxDynamicSharedMemorySize, NODE_SMEM_BYTES);
    cudaFuncSetAttribute(pre_kernel,  cudaFuncAttributeMaxDynamicSharedMemorySize, P_SMEM_BYTES);

    const size_t XB = (size_t)N_NODES * 3 * sizeof(float);
    const int EGRID = 608;   // 4 CTAs/SM x 152

    init_kernel<<<(N_NODES * HID + 255) / 256, 256>>>(z, emb, t, tw1, tb1, tw2, tb2, B);

    // ---- layer 0 ----
    pre_kernel<<<304, 192, P_SMEM_BYTES>>>(ew1 + 0 * 129 * 64, eb1 + 0 * 64);
    cudaMemcpyAsync(pxB, x, XB, cudaMemcpyDeviceToDevice, 0);
    edge_kernel<<<EGRID, 128, EDGE_SMEM_BYTES>>>(x, pxB, ei,
        ew1 + 0 * 129 * 64 + 128 * 64, ew2 + 0 * 4096, eb2 + 0 * 64,
        cw1 + 0 * 4096, cb1 + 0 * 64, cw2 + 0 * 64, cb2 + 0, 1);
    node_kernel<<<152, 384, NODE_SMEM_BYTES>>>(nw1 + 0 * 128 * 64, nb1 + 0 * 64,
                                               nw2 + 0 * 4096, nb2 + 0 * 64,
                                               ew1 + 1 * 129 * 64, eb1 + 1 * 64);
    dummy_kernel<<<1, 32>>>();

    // ---- layer 1 ----
    cudaMemcpyAsync(pxA, pxB, XB, cudaMemcpyDeviceToDevice, 0);
    edge_kernel<<<EGRID, 128, EDGE_SMEM_BYTES>>>(pxB, pxA, ei,
        ew1 + 1 * 129 * 64 + 128 * 64, ew2 + 1 * 4096, eb2 + 1 * 64,
        cw1 + 1 * 4096, cb1 + 1 * 64, cw2 + 1 * 64, cb2 + 1, 1);
    node_kernel<<<152, 384, NODE_SMEM_BYTES>>>(nw1 + 1 * 128 * 64, nb1 + 1 * 64,
                                               nw2 + 1 * 4096, nb2 + 1 * 64,
                                               ew1 + 2 * 129 * 64, eb1 + 2 * 64);

    // ---- layer 2: agg/node dead, write x' straight to d_out ----
    cudaMemcpyAsync(out, pxA, XB, cudaMemcpyDeviceToDevice, 0);
    edge_kernel<<<EGRID, 128, EDGE_SMEM_BYTES>>>(pxA, out, ei,
        ew1 + 2 * 129 * 64 + 128 * 64, ew2 + 2 * 4096, eb2 + 2 * 64,
        cw1 + 2 * 4096, cb1 + 2 * 64, cw2 + 2 * 64, cb2 + 2, 0);
}

// round 15
// speedup vs baseline: 1.3968x; 1.0548x over previous
#include <cuda_runtime.h>
#include <cuda_fp16.h>
#include <cstdint>

#define N_NODES 100000
#define N_EDGES 1600000
#define HID 64
#define NGROUPS (N_EDGES / 32)       // 50000
#define NODE_GROUPS (N_NODES / 32)   // 3125

// ---------- device scratch ----------
__device__ float g_h[N_NODES * HID];
__device__ float g_agg[N_NODES * HID];
__device__ float g_P[N_NODES * HID];
__device__ float g_Q[N_NODES * HID];
__device__ float g_xA[N_NODES * 3];
__device__ float g_xB[N_NODES * 3];

// ---------- helpers ----------
__device__ __forceinline__ float silu(float v) {
    float u = 0.5f * v, th;
    asm("tanh.approx.f32 %0, %1;" : "=f"(th) : "f"(u));
    return v * fmaf(th, 0.5f, 0.5f);
}
__device__ __forceinline__ void red_add_v4(float* addr, float a, float b, float c, float d) {
    asm volatile("red.global.add.v4.f32 [%0], {%1, %2, %3, %4};"
                 :: "l"(addr), "f"(a), "f"(b), "f"(c), "f"(d) : "memory");
}
__device__ __forceinline__ uint32_t f16_pack2(float f0, float f1) {
    uint32_t h;
    asm("cvt.rn.f16x2.f32 %0, %1, %2;" : "=r"(h) : "f"(f1), "f"(f0));
    return h;
}
__device__ __forceinline__ void mma16816(float c[4], const uint32_t a[4],
                                         uint32_t b0, uint32_t b1) {
    asm volatile(
        "mma.sync.aligned.m16n8k16.row.col.f32.f16.f16.f32 "
        "{%0,%1,%2,%3}, {%4,%5,%6,%7}, {%8,%9}, {%0,%1,%2,%3};"
        : "+f"(c[0]), "+f"(c[1]), "+f"(c[2]), "+f"(c[3])
        : "r"(a[0]), "r"(a[1]), "r"(a[2]), "r"(a[3]), "r"(b0), "r"(b1));
}
// stage 64x64 fp32 weight (row-major [k][n]) as f16 B-tile [n][kk] u32 words, stride 36
__device__ __forceinline__ void stage_btile(uint32_t* dst,
                                            const float* __restrict__ W, int tid, int nth) {
    for (int i = tid; i < 2048; i += nth) {
        int n = i >> 5, kk = i & 31;
        dst[n * 36 + kk] = f16_pack2(W[(2 * kk) * 64 + n], W[(2 * kk + 1) * 64 + n]);
    }
}
// 1-term K=64 mma, A from smem
__device__ __forceinline__ void mma1_smem(float acc[16][4],
                                          const uint32_t* __restrict__ Ah,
                                          const uint32_t* __restrict__ Bh,
                                          int g, int t) {
    #pragma unroll
    for (int kt = 0; kt < 4; kt++) {
        uint32_t ah[2][4];
        #pragma unroll
        for (int mt = 0; mt < 2; mt++) {
            int rb = (16 * mt + g) * 36 + 8 * kt + t;
            ah[mt][0] = Ah[rb];     ah[mt][1] = Ah[rb + 8 * 36];
            ah[mt][2] = Ah[rb + 4]; ah[mt][3] = Ah[rb + 8 * 36 + 4];
        }
        #pragma unroll
        for (int nt = 0; nt < 8; nt++) {
            int bi = (8 * nt + g) * 36 + 8 * kt + t;
            uint32_t bh0 = Bh[bi], bh1 = Bh[bi + 4];
            #pragma unroll
            for (int mt = 0; mt < 2; mt++)
                mma16816(acc[mt * 8 + nt], ah[mt], bh0, bh1);
        }
    }
}
// 1-term K=64 mma, A from register fragments
__device__ __forceinline__ void mma1_reg(float acc[16][4],
                                         const uint32_t fh[2][4][4],
                                         const uint32_t* __restrict__ Bh,
                                         int g, int t) {
    #pragma unroll
    for (int kt = 0; kt < 4; kt++) {
        #pragma unroll
        for (int nt = 0; nt < 8; nt++) {
            int bi = (8 * nt + g) * 36 + 8 * kt + t;
            uint32_t bh0 = Bh[bi], bh1 = Bh[bi + 4];
            #pragma unroll
            for (int mt = 0; mt < 2; mt++)
                mma16816(acc[mt * 8 + nt], fh[mt][kt], bh0, bh1);
        }
    }
}

__global__ void dummy_kernel() {}

// ---------- fused init+pre: h = emb[z]+tmean, agg = 0, P = h@W1a+b1, Q = h@W1b ----------
#define IP_A   0
#define IP_B   2304
#define IP_B1  4608
#define IP_TM  4672
#define IP_WBASE 4736
#define IP_WW  1152
#define IP_SMEM_WORDS (IP_WBASE + 6 * IP_WW)
#define IP_SMEM_BYTES (IP_SMEM_WORDS * 4)

__global__ void __launch_bounds__(192)
initpre_kernel(const int* __restrict__ z, const float* __restrict__ emb,
               const float* __restrict__ t,
               const float* __restrict__ tw1, const float* __restrict__ tb1,
               const float* __restrict__ tw2, const float* __restrict__ tb2,
               int B,
               const float* __restrict__ ew1, const float* __restrict__ eb1g) {
    extern __shared__ uint32_t smw[];
    float* smf = (float*)smw;
    const int tid = threadIdx.x;

    stage_btile(smw + IP_A, ew1, tid, 192);
    stage_btile(smw + IP_B, ew1 + 64 * 64, tid, 192);
    if (tid < 64) smf[IP_B1 + tid] = eb1g[tid];
    // compute tmean
    __shared__ float s1[64];
    if (tid < 64) {
        float w = tw1[tid], bb = tb1[tid];
        float acc = 0.f;
        for (int b = 0; b < B; b++) acc += silu(t[b] * w + bb);
        s1[tid] = acc / (float)B;
    }
    __syncthreads();
    if (tid < 64) {
        float o = tb2[tid];
        for (int k = 0; k < 64; k++) o += s1[k] * tw2[k * 64 + tid];
        smf[IP_TM + tid] = o;
    }
    __syncthreads();

    const int lane = tid & 31;
    const int wrp = tid >> 5;
    const int g = lane >> 2;
    const int t4 = lane & 3;
    uint32_t* Ah = smw + IP_WBASE + wrp * IP_WW;
    const float tm0 = smf[IP_TM + 2 * lane];
    const float tm1 = smf[IP_TM + 2 * lane + 1];

    const int gwarp = (blockIdx.x * 192 + tid) >> 5;
    const int nwarps = (gridDim.x * 192) >> 5;

    for (int grp = gwarp; grp < NODE_GROUPS; grp += nwarps) {
        const int base = grp * 32;
        const int zv = __ldg(&z[base + lane]);
        __syncwarp();
        #pragma unroll
        for (int e2 = 0; e2 < 32; e2++) {
            int nz = __shfl_sync(0xffffffffu, zv, e2);
            float2 ev = __ldg((const float2*)(emb + (size_t)nz * 64 + 2 * lane));
            float h0 = ev.x + tm0, h1 = ev.y + tm1;
            size_t idx = (size_t)(base + e2) * 64 + 2 * lane;
            *(float2*)(g_h + idx) = make_float2(h0, h1);
            *(float2*)(g_agg + idx) = make_float2(0.f, 0.f);
            Ah[e2 * 36 + lane] = f16_pack2(h0, h1);
        }
        __syncwarp();

        float accP[16][4], accQ[16][4];
        #pragma unroll
        for (int nt = 0; nt < 8; nt++) {
            float2 bb = *(const float2*)(smf + IP_B1 + 8 * nt + 2 * t4);
            #pragma unroll
            for (int mt = 0; mt < 2; mt++) {
                accP[mt * 8 + nt][0] = bb.x; accP[mt * 8 + nt][1] = bb.y;
                accP[mt * 8 + nt][2] = bb.x; accP[mt * 8 + nt][3] = bb.y;
                accQ[mt * 8 + nt][0] = 0.f; accQ[mt * 8 + nt][1] = 0.f;
                accQ[mt * 8 + nt][2] = 0.f; accQ[mt * 8 + nt][3] = 0.f;
            }
        }
        mma1_smem(accP, Ah, smw + IP_A, g, t4);
        mma1_smem(accQ, Ah, smw + IP_B, g, t4);
        #pragma unroll
        for (int mt = 0; mt < 2; mt++) {
            int r1 = base + 16 * mt + g;
            int r2 = r1 + 8;
            #pragma unroll
            for (int nt = 0; nt < 8; nt++) {
                int c = 8 * nt + 2 * t4;
                *(float2*)(g_P + (size_t)r1 * 64 + c) = make_float2(accP[mt * 8 + nt][0], accP[mt * 8 + nt][1]);
                *(float2*)(g_P + (size_t)r2 * 64 + c) = make_float2(accP[mt * 8 + nt][2], accP[mt * 8 + nt][3]);
                *(float2*)(g_Q + (size_t)r1 * 64 + c) = make_float2(accQ[mt * 8 + nt][0], accQ[mt * 8 + nt][1]);
                *(float2*)(g_Q + (size_t)r2 * 64 + c) = make_float2(accQ[mt * 8 + nt][2], accQ[mt * 8 + nt][3]);
            }
        }
    }
}

// ---------- edge kernel (fp16 1-term, 4 CTAs/SM) — unchanged from R14 ----------
#define B_W2H  0
#define B_C1H  2304
#define SC_W1C 4608
#define SC_B2  4672
#define SC_CB1 4736
#define SC_CW2 4800
#define SC_CB2 4864
#define WARP_BASE 4868
#define WARP_W 1152
#define EDGE_SMEM_WORDS (WARP_BASE + 4 * WARP_W)
#define EDGE_SMEM_BYTES (EDGE_SMEM_WORDS * 4)   // 37,904 B -> 4 CTAs/SM

__global__ void __launch_bounds__(128, 4)
edge_kernel(const float* __restrict__ x, float* __restrict__ xn,
            const int* __restrict__ ei,
            const float* __restrict__ w1c_g,
            const float* __restrict__ ew2, const float* __restrict__ eb2g,
            const float* __restrict__ cw1, const float* __restrict__ cb1g,
            const float* __restrict__ cw2g, const float* __restrict__ cb2g,
            int do_agg) {
    extern __shared__ uint32_t smw[];
    float* smf = (float*)smw;
    const int tid = threadIdx.x;

    stage_btile(smw + B_W2H, ew2, tid, 128);
    stage_btile(smw + B_C1H, cw1, tid, 128);
    if (tid < 64) {
        smf[SC_W1C + tid] = w1c_g[tid];
        smf[SC_B2 + tid]  = eb2g[tid];
        smf[SC_CB1 + tid] = cb1g[tid];
        smf[SC_CW2 + tid] = cw2g[tid];
    }
    if (tid == 0) smf[SC_CB2] = cb2g[0];
    __syncthreads();

    const int lane = tid & 31;
    const int wrp = tid >> 5;
    const int g = lane >> 2;
    const int t = lane & 3;
    uint32_t* Ah = smw + WARP_BASE + wrp * WARP_W;
    const float w1c0 = smf[SC_W1C + 2 * lane];
    const float w1c1 = smf[SC_W1C + 2 * lane + 1];
    const float cb2s = smf[SC_CB2];

    const int gwarp = (blockIdx.x * 128 + tid) >> 5;
    const int nwarps = (gridDim.x * 128) >> 5;

    int grp = gwarp;
    int s_n = 0, d_n = 0;
    float xs0 = 0, xs1 = 0, xs2 = 0, xd0 = 0, xd1 = 0, xd2 = 0;
    if (grp < NGROUPS) {
        int e = grp * 32 + lane;
        s_n = ei[e]; d_n = ei[N_EDGES + e];
        xs0 = __ldg(&x[s_n * 3 + 0]); xs1 = __ldg(&x[s_n * 3 + 1]); xs2 = __ldg(&x[s_n * 3 + 2]);
        xd0 = __ldg(&x[d_n * 3 + 0]); xd1 = __ldg(&x[d_n * 3 + 1]); xd2 = __ldg(&x[d_n * 3 + 2]);
    }

    for (; grp < NGROUPS; grp += nwarps) {
        const int s = s_n, d = d_n;
        const float dx0 = xd0 - xs0;
        const float dx1 = xd1 - xs1;
        const float dx2 = xd2 - xs2;
        const float r2 = dx0 * dx0 + dx1 * dx1 + dx2 * dx2;

        __syncwarp();
        #pragma unroll 16
        for (int e2 = 0; e2 < 32; e2++) {
            int nd = __shfl_sync(0xffffffffu, d, e2);
            int ns = __shfl_sync(0xffffffffu, s, e2);
            float rr = __shfl_sync(0xffffffffu, r2, e2);
            float2 pv = __ldg((const float2*)(g_P + (size_t)nd * 64 + 2 * lane));
            float2 qv = __ldg((const float2*)(g_Q + (size_t)ns * 64 + 2 * lane));
            float f0 = silu(fmaf(rr, w1c0, pv.x + qv.x));
            float f1 = silu(fmaf(rr, w1c1, pv.y + qv.y));
            Ah[e2 * 36 + lane] = f16_pack2(f0, f1);
        }
        __syncwarp();

        {
            int gn = grp + nwarps;
            if (gn < NGROUPS) {
                int e = gn * 32 + lane;
                s_n = ei[e]; d_n = ei[N_EDGES + e];
                xs0 = __ldg(&x[s_n * 3 + 0]); xs1 = __ldg(&x[s_n * 3 + 1]); xs2 = __ldg(&x[s_n * 3 + 2]);
                xd0 = __ldg(&x[d_n * 3 + 0]); xd1 = __ldg(&x[d_n * 3 + 1]); xd2 = __ldg(&x[d_n * 3 + 2]);
            }
        }

        // ---- matmul1: D = ef1 @ W2 + b2 ----
        float acc[16][4];
        #pragma unroll
        for (int nt = 0; nt < 8; nt++) {
            float2 bb = *(const float2*)(smf + SC_B2 + 8 * nt + 2 * t);
            #pragma unroll
            for (int mt = 0; mt < 2; mt++) {
                acc[mt * 8 + nt][0] = bb.x; acc[mt * 8 + nt][1] = bb.y;
                acc[mt * 8 + nt][2] = bb.x; acc[mt * 8 + nt][3] = bb.y;
            }
        }
        mma1_smem(acc, Ah, smw + B_W2H, g, t);

        // ---- m = silu(D); paired red.v4; pack to matmul2 A frags ----
        uint32_t mh[2][4][4];
        int dtop[2], dbot[2];
        #pragma unroll
        for (int mt = 0; mt < 2; mt++) {
            dtop[mt] = __shfl_sync(0xffffffffu, d, 16 * mt + g);
            dbot[mt] = __shfl_sync(0xffffffffu, d, 16 * mt + g + 8);
        }
        const int colbase_off = 2 * (t & ~1);
        #pragma unroll
        for (int mt = 0; mt < 2; mt++) {
            #pragma unroll
            for (int nt = 0; nt < 8; nt++) {
                float v0 = silu(acc[mt * 8 + nt][0]);
                float v1 = silu(acc[mt * 8 + nt][1]);
                float v2 = silu(acc[mt * 8 + nt][2]);
                float v3 = silu(acc[mt * 8 + nt][3]);
                if (do_agg) {
                    float px = (t & 1) ? v0 : v2;
                    float qx = (t & 1) ? v1 : v3;
                    float pr = __shfl_xor_sync(0xffffffffu, px, 1);
                    float qr = __shfl_xor_sync(0xffffffffu, qx, 1);
                    int row = (t & 1) ? dbot[mt] : dtop[mt];
                    int col = 8 * nt + colbase_off;
                    float a0 = (t & 1) ? pr : v0;
                    float a1 = (t & 1) ? qr : v1;
                    float a2 = (t & 1) ? v2 : pr;
                    float a3 = (t & 1) ? v3 : qr;
                    red_add_v4(&g_agg[(size_t)row * 64 + col], a0, a1, a2, a3);
                }
                int kt = nt >> 1, o = (nt & 1) * 2;
                mh[mt][kt][o]     = f16_pack2(v0, v1);
                mh[mt][kt][o + 1] = f16_pack2(v2, v3);
            }
        }

        // ---- matmul2: D2 = m @ C1 + cb1 ----
        float acc2[16][4];
        #pragma unroll
        for (int nt = 0; nt < 8; nt++) {
            float2 bb = *(const float2*)(smf + SC_CB1 + 8 * nt + 2 * t);
            #pragma unroll
            for (int mt = 0; mt < 2; mt++) {
                acc2[mt * 8 + nt][0] = bb.x; acc2[mt * 8 + nt][1] = bb.y;
                acc2[mt * 8 + nt][2] = bb.x; acc2[mt * 8 + nt][3] = bb.y;
            }
        }
        mma1_reg(acc2, mh, smw + B_C1H, g, t);

        // ---- coord epilogue ----
        float pr0 = 0.f, pr1 = 0.f, pr2 = 0.f, pr3 = 0.f;
        #pragma unroll
        for (int nt = 0; nt < 8; nt++) {
            float2 cwv = *(const float2*)(smf + SC_CW2 + 8 * nt + 2 * t);
            pr0 = fmaf(silu(acc2[nt][0]), cwv.x, pr0);
            pr0 = fmaf(silu(acc2[nt][1]), cwv.y, pr0);
            pr1 = fmaf(silu(acc2[nt][2]), cwv.x, pr1);
            pr1 = fmaf(silu(acc2[nt][3]), cwv.y, pr1);
            pr2 = fmaf(silu(acc2[8 + nt][0]), cwv.x, pr2);
            pr2 = fmaf(silu(acc2[8 + nt][1]), cwv.y, pr2);
            pr3 = fmaf(silu(acc2[8 + nt][2]), cwv.x, pr3);
            pr3 = fmaf(silu(acc2[8 + nt][3]), cwv.y, pr3);
        }
        pr0 += __shfl_xor_sync(0xffffffffu, pr0, 1);
        pr0 += __shfl_xor_sync(0xffffffffu, pr0, 2);
        pr1 += __shfl_xor_sync(0xffffffffu, pr1, 1);
        pr1 += __shfl_xor_sync(0xffffffffu, pr1, 2);
        pr2 += __shfl_xor_sync(0xffffffffu, pr2, 1);
        pr2 += __shfl_xor_sync(0xffffffffu, pr2, 2);
        pr3 += __shfl_xor_sync(0xffffffffu, pr3, 1);
        pr3 += __shfl_xor_sync(0xffffffffu, pr3, 2);
        float p = (t == 0) ? pr0 : (t == 1) ? pr1 : (t == 2) ? pr2 : pr3;
        const int e2l = g + 8 * t;
        p += cb2s;
        int dd = __shfl_sync(0xffffffffu, d, e2l);
        float ddx0 = __shfl_sync(0xffffffffu, dx0, e2l);
        float ddx1 = __shfl_sync(0xffffffffu, dx1, e2l);
        float ddx2 = __shfl_sync(0xffffffffu, dx2, e2l);
        atomicAdd(&xn[dd * 3 + 0], ddx0 * p);
        atomicAdd(&xn[dd * 3 + 1], ddx1 * p);
        atomicAdd(&xn[dd * 3 + 2], ddx2 * p);
    }
}

// ---------- node kernel (fp16 1-term) + fused next-layer P/Q — unchanged from R14 ----------
#define N_W1H  0
#define N_W1A  2304
#define N_W2   4608
#define N_PA   6912
#define N_PB   9216
#define N_B1W  11520
#define N_B2W  11584
#define N_EB1W 11648
#define N_ABASE 11712
#define N_AW   1152
#define NODE_SMEM_WORDS (N_ABASE + 12 * N_AW)
#define NODE_SMEM_BYTES (NODE_SMEM_WORDS * 4)   // 102,144 B -> 1 CTA/SM at 384 thr

__global__ void __launch_bounds__(384)
node_kernel(const float* __restrict__ nw1, const float* __restrict__ nb1g,
            const float* __restrict__ nw2, const float* __restrict__ nb2g,
            const float* __restrict__ ew1n, const float* __restrict__ eb1n) {
    extern __shared__ uint32_t smw[];
    float* smf = (float*)smw;
    const int tid = threadIdx.x;

    stage_btile(smw + N_W1H, nw1, tid, 384);
    stage_btile(smw + N_W1A, nw1 + 64 * 64, tid, 384);
    stage_btile(smw + N_W2, nw2, tid, 384);
    stage_btile(smw + N_PA, ew1n, tid, 384);
    stage_btile(smw + N_PB, ew1n + 64 * 64, tid, 384);
    if (tid < 64) {
        smf[N_B1W + tid]  = nb1g[tid];
        smf[N_B2W + tid]  = nb2g[tid];
        smf[N_EB1W + tid] = eb1n[tid];
    }
    __syncthreads();

    const int lane = tid & 31;
    const int wrp = tid >> 5;
    const int g = lane >> 2;
    const int t = lane & 3;
    uint32_t* Ah = smw + N_ABASE + wrp * N_AW;

    const int gwarp = (blockIdx.x * 384 + tid) >> 5;
    const int nwarps = (gridDim.x * 384) >> 5;

    for (int grp = gwarp; grp < NODE_GROUPS; grp += nwarps) {
        const int base = grp * 32;

        __syncwarp();
        #pragma unroll
        for (int e2 = 0; e2 < 32; e2++) {
            float2 hv = __ldg((const float2*)(g_h + (size_t)(base + e2) * 64 + 2 * lane));
            Ah[e2 * 36 + lane] = f16_pack2(hv.x, hv.y);
        }
        __syncwarp();

        float acc1[16][4];
        #pragma unroll
        for (int nt = 0; nt < 8; nt++) {
            float2 bb = *(const float2*)(smf + N_B1W + 8 * nt + 2 * t);
            #pragma unroll
            for (int mt = 0; mt < 2; mt++) {
                acc1[mt * 8 + nt][0] = bb.x; acc1[mt * 8 + nt][1] = bb.y;
                acc1[mt * 8 + nt][2] = bb.x; acc1[mt * 8 + nt][3] = bb.y;
            }
        }
        mma1_smem(acc1, Ah, smw + N_W1H, g, t);

        __syncwarp();
        #pragma unroll
        for (int e2 = 0; e2 < 32; e2++) {
            float2* ap = (float2*)(g_agg + (size_t)(base + e2) * 64 + 2 * lane);
            float2 av = *ap;
            *ap = make_float2(0.f, 0.f);
            Ah[e2 * 36 + lane] = f16_pack2(av.x, av.y);
        }
        __syncwarp();
        mma1_smem(acc1, Ah, smw + N_W1A, g, t);

        uint32_t mh[2][4][4];
        #pragma unroll
        for (int mt = 0; mt < 2; mt++) {
            #pragma unroll
            for (int nt = 0; nt < 8; nt++) {
                float v0 = silu(acc1[mt * 8 + nt][0]);
                float v1 = silu(acc1[mt * 8 + nt][1]);
                float v2 = silu(acc1[mt * 8 + nt][2]);
                float v3 = silu(acc1[mt * 8 + nt][3]);
                int kt = nt >> 1, o = (nt & 1) * 2;
                mh[mt][kt][o]     = f16_pack2(v0, v1);
                mh[mt][kt][o + 1] = f16_pack2(v2, v3);
            }
        }

        float acc2[16][4];
        #pragma unroll
        for (int nt = 0; nt < 8; nt++) {
            float2 bb = *(const float2*)(smf + N_B2W + 8 * nt + 2 * t);
            #pragma unroll
            for (int mt = 0; mt < 2; mt++) {
                acc2[mt * 8 + nt][0] = bb.x; acc2[mt * 8 + nt][1] = bb.y;
                acc2[mt * 8 + nt][2] = bb.x; acc2[mt * 8 + nt][3] = bb.y;
            }
        }
        mma1_reg(acc2, mh, smw + N_W2, g, t);

        uint32_t hh[2][4][4];
        #pragma unroll
        for (int mt = 0; mt < 2; mt++) {
            int r1 = base + 16 * mt + g;
            int r2 = r1 + 8;
            #pragma unroll
            for (int nt = 0; nt < 8; nt++) {
                int c = 8 * nt + 2 * t;
                float2 h1 = __ldg((const float2*)(g_h + (size_t)r1 * 64 + c));
                float2 h2 = __ldg((const float2*)(g_h + (size_t)r2 * 64 + c));
                float v0 = h1.x + acc2[mt * 8 + nt][0];
                float v1 = h1.y + acc2[mt * 8 + nt][1];
                float v2 = h2.x + acc2[mt * 8 + nt][2];
                float v3 = h2.y + acc2[mt * 8 + nt][3];
                *(float2*)(g_h + (size_t)r1 * 64 + c) = make_float2(v0, v1);
                *(float2*)(g_h + (size_t)r2 * 64 + c) = make_float2(v2, v3);
                int kt = nt >> 1, o = (nt & 1) * 2;
                hh[mt][kt][o]     = f16_pack2(v0, v1);
                hh[mt][kt][o + 1] = f16_pack2(v2, v3);
            }
        }

        float accp[16][4];
        #pragma unroll
        for (int nt = 0; nt < 8; nt++) {
            float2 bb = *(const float2*)(smf + N_EB1W + 8 * nt + 2 * t);
            #pragma unroll
            for (int mt = 0; mt < 2; mt++) {
                accp[mt * 8 + nt][0] = bb.x; accp[mt * 8 + nt][1] = bb.y;
                accp[mt * 8 + nt][2] = bb.x; accp[mt * 8 + nt][3] = bb.y;
            }
        }
        mma1_reg(accp, hh, smw + N_PA, g, t);
        #pragma unroll
        for (int mt = 0; mt < 2; mt++) {
            int r1 = base + 16 * mt + g;
            int r2 = r1 + 8;
            #pragma unroll
            for (int nt = 0; nt < 8; nt++) {
                int c = 8 * nt + 2 * t;
                *(float2*)(g_P + (size_t)r1 * 64 + c) = make_float2(accp[mt * 8 + nt][0], accp[mt * 8 + nt][1]);
                *(float2*)(g_P + (size_t)r2 * 64 + c) = make_float2(accp[mt * 8 + nt][2], accp[mt * 8 + nt][3]);
            }
        }

        #pragma unroll
        for (int a = 0; a < 16; a++) {
            accp[a][0] = 0.f; accp[a][1] = 0.f; accp[a][2] = 0.f; accp[a][3] = 0.f;
        }
        mma1_reg(accp, hh, smw + N_PB, g, t);
        #pragma unroll
        for (int mt = 0; mt < 2; mt++) {
            int r1 = base + 16 * mt + g;
            int r2 = r1 + 8;
            #pragma unroll
            for (int nt = 0; nt < 8; nt++) {
                int c = 8 * nt + 2 * t;
                *(float2*)(g_Q + (size_t)r1 * 64 + c) = make_float2(accp[mt * 8 + nt][0], accp[mt * 8 + nt][1]);
                *(float2*)(g_Q + (size_t)r2 * 64 + c) = make_float2(accp[mt * 8 + nt][2], accp[mt * 8 + nt][3]);
            }
        }
    }
}

// ---------- launch ----------
extern "C" void kernel_launch(void* const* d_in, const int* in_sizes, int n_in,
                              void* d_out, int out_size) {
    const float* x   = (const float*)d_in[0];
    const int*   z   = (const int*)d_in[1];
    const float* t   = (const float*)d_in[2];
    const int*   ei  = (const int*)d_in[3];
    const float* emb = (const float*)d_in[4];
    const float* tw1 = (const float*)d_in[5];
    const float* tb1 = (const float*)d_in[6];
    const float* tw2 = (const float*)d_in[7];
    const float* tb2 = (const float*)d_in[8];
    const float* ew1 = (const float*)d_in[9];
    const float* eb1 = (const float*)d_in[10];
    const float* ew2 = (const float*)d_in[11];
    const float* eb2 = (const float*)d_in[12];
    const float* cw1 = (const float*)d_in[13];
    const float* cb1 = (const float*)d_in[14];
    const float* cw2 = (const float*)d_in[15];
    const float* cb2 = (const float*)d_in[16];
    const float* nw1 = (const float*)d_in[17];
    const float* nb1 = (const float*)d_in[18];
    const float* nw2 = (const float*)d_in[19];
    const float* nb2 = (const float*)d_in[20];
    float* out = (float*)d_out;
    const int B = in_sizes[2];

    float *pxA, *pxB;
    cudaGetSymbolAddress((void**)&pxA, g_xA);
    cudaGetSymbolAddress((void**)&pxB, g_xB);

    cudaFuncSetAttribute(edge_kernel, cudaFuncAttributeMaxDynamicSharedMemorySize, EDGE_SMEM_BYTES);
    cudaFuncSetAttribute(node_kernel, cudaFuncAttributeMaxDynamicSharedMemorySize, NODE_SMEM_BYTES);
    cudaFuncSetAttribute(initpre_kernel, cudaFuncAttributeMaxDynamicSharedMemorySize, IP_SMEM_BYTES);

    const size_t XB = (size_t)N_NODES * 3 * sizeof(float);
    const int EGRID = 608;   // 4 CTAs/SM x 152

    // launches: 0 initpre, 1 edge0, 2 node0, 3 dummy, 4 dummy, 5 edge1 (ncu -s 5 target)
    initpre_kernel<<<304, 192, IP_SMEM_BYTES>>>(z, emb, t, tw1, tb1, tw2, tb2, B,
                                                ew1 + 0 * 129 * 64, eb1 + 0 * 64);

    // ---- layer 0 ----
    cudaMemcpyAsync(pxB, x, XB, cudaMemcpyDeviceToDevice, 0);
    edge_kernel<<<EGRID, 128, EDGE_SMEM_BYTES>>>(x, pxB, ei,
        ew1 + 0 * 129 * 64 + 128 * 64, ew2 + 0 * 4096, eb2 + 0 * 64,
        cw1 + 0 * 4096, cb1 + 0 * 64, cw2 + 0 * 64, cb2 + 0, 1);
    node_kernel<<<152, 384, NODE_SMEM_BYTES>>>(nw1 + 0 * 128 * 64, nb1 + 0 * 64,
                                               nw2 + 0 * 4096, nb2 + 0 * 64,
                                               ew1 + 1 * 129 * 64, eb1 + 1 * 64);
    dummy_kernel<<<1, 32>>>();
    dummy_kernel<<<1, 32>>>();

    // ---- layer 1 ----
    cudaMemcpyAsync(pxA, pxB, XB, cudaMemcpyDeviceToDevice, 0);
    edge_kernel<<<EGRID, 128, EDGE_SMEM_BYTES>>>(pxB, pxA, ei,
        ew1 + 1 * 129 * 64 + 128 * 64, ew2 + 1 * 4096, eb2 + 1 * 64,
        cw1 + 1 * 4096, cb1 + 1 * 64, cw2 + 1 * 64, cb2 + 1, 1);
    node_kernel<<<152, 384, NODE_SMEM_BYTES>>>(nw1 + 1 * 128 * 64, nb1 + 1 * 64,
                                               nw2 + 1 * 4096, nb2 + 1 * 64,
                                               ew1 + 2 * 129 * 64, eb1 + 2 * 64);

    // ---- layer 2: agg/node dead, write x' straight to d_out ----
    cudaMemcpyAsync(out, pxA, XB, cudaMemcpyDeviceToDevice, 0);
    edge_kernel<<<EGRID, 128, EDGE_SMEM_BYTES>>>(pxA, out, ei,
        ew1 + 2 * 129 * 64 + 128 * 64, ew2 + 2 * 4096, eb2 + 2 * 64,
        cw1 + 2 * 4096, cb1 + 2 * 64, cw2 + 2 * 64, cb2 + 2, 0);
}

// round 16
// speedup vs baseline: 1.4022x; 1.0039x over previous
#include <cuda_runtime.h>
#include <cuda_fp16.h>
#include <cstdint>

#define N_NODES 100000
#define N_EDGES 1600000
#define HID 64
#define NGROUPS (N_EDGES / 32)       // 50000
#define NODE_GROUPS (N_NODES / 32)   // 3125

// ---------- device scratch ----------
__device__ float g_h[N_NODES * HID];
__device__ float g_agg[N_NODES * HID];
__device__ float g_P[N_NODES * HID];
__device__ float g_Q[N_NODES * HID];
__device__ float g_xA[N_NODES * 3];
__device__ float g_xB[N_NODES * 3];

// ---------- helpers ----------
__device__ __forceinline__ float silu(float v) {
    float u = 0.5f * v, th;
    asm("tanh.approx.f32 %0, %1;" : "=f"(th) : "f"(u));
    return v * fmaf(th, 0.5f, 0.5f);
}
__device__ __forceinline__ void red_add_v4(float* addr, float a, float b, float c, float d) {
    asm volatile("red.global.add.v4.f32 [%0], {%1, %2, %3, %4};"
                 :: "l"(addr), "f"(a), "f"(b), "f"(c), "f"(d) : "memory");
}
__device__ __forceinline__ uint32_t f16_pack2(float f0, float f1) {
    uint32_t h;
    asm("cvt.rn.f16x2.f32 %0, %1, %2;" : "=r"(h) : "f"(f1), "f"(f0));
    return h;
}
__device__ __forceinline__ void mma16816(float c[4], const uint32_t a[4],
                                         uint32_t b0, uint32_t b1) {
    asm volatile(
        "mma.sync.aligned.m16n8k16.row.col.f32.f16.f16.f32 "
        "{%0,%1,%2,%3}, {%4,%5,%6,%7}, {%8,%9}, {%0,%1,%2,%3};"
        : "+f"(c[0]), "+f"(c[1]), "+f"(c[2]), "+f"(c[3])
        : "r"(a[0]), "r"(a[1]), "r"(a[2]), "r"(a[3]), "r"(b0), "r"(b1));
}
// stage 64x64 fp32 weight (row-major [k][n]) as f16 B-tile [n][kk] u32 words, stride 36
__device__ __forceinline__ void stage_btile(uint32_t* dst,
                                            const float* __restrict__ W, int tid, int nth) {
    for (int i = tid; i < 2048; i += nth) {
        int n = i >> 5, kk = i & 31;
        dst[n * 36 + kk] = f16_pack2(W[(2 * kk) * 64 + n], W[(2 * kk + 1) * 64 + n]);
    }
}
// 1-term K=64 mma, A from smem
__device__ __forceinline__ void mma1_smem(float acc[16][4],
                                          const uint32_t* __restrict__ Ah,
                                          const uint32_t* __restrict__ Bh,
                                          int g, int t) {
    #pragma unroll
    for (int kt = 0; kt < 4; kt++) {
        uint32_t ah[2][4];
        #pragma unroll
        for (int mt = 0; mt < 2; mt++) {
            int rb = (16 * mt + g) * 36 + 8 * kt + t;
            ah[mt][0] = Ah[rb];     ah[mt][1] = Ah[rb + 8 * 36];
            ah[mt][2] = Ah[rb + 4]; ah[mt][3] = Ah[rb + 8 * 36 + 4];
        }
        #pragma unroll
        for (int nt = 0; nt < 8; nt++) {
            int bi = (8 * nt + g) * 36 + 8 * kt + t;
            uint32_t bh0 = Bh[bi], bh1 = Bh[bi + 4];
            #pragma unroll
            for (int mt = 0; mt < 2; mt++)
                mma16816(acc[mt * 8 + nt], ah[mt], bh0, bh1);
        }
    }
}
// 1-term K=64 mma, A from register fragments
__device__ __forceinline__ void mma1_reg(float acc[16][4],
                                         const uint32_t fh[2][4][4],
                                         const uint32_t* __restrict__ Bh,
                                         int g, int t) {
    #pragma unroll
    for (int kt = 0; kt < 4; kt++) {
        #pragma unroll
        for (int nt = 0; nt < 8; nt++) {
            int bi = (8 * nt + g) * 36 + 8 * kt + t;
            uint32_t bh0 = Bh[bi], bh1 = Bh[bi + 4];
            #pragma unroll
            for (int mt = 0; mt < 2; mt++)
                mma16816(acc[mt * 8 + nt], fh[mt][kt], bh0, bh1);
        }
    }
}

// ---------- fused init+pre: h = emb[z]+tmean, agg = 0, P = h@W1a+b1, Q = h@W1b ----------
#define IP_A   0
#define IP_B   2304
#define IP_B1  4608
#define IP_TM  4672
#define IP_WBASE 4736
#define IP_WW  1152
#define IP_SMEM_WORDS (IP_WBASE + 6 * IP_WW)
#define IP_SMEM_BYTES (IP_SMEM_WORDS * 4)

__global__ void __launch_bounds__(192)
initpre_kernel(const int* __restrict__ z, const float* __restrict__ emb,
               const float* __restrict__ t,
               const float* __restrict__ tw1, const float* __restrict__ tb1,
               const float* __restrict__ tw2, const float* __restrict__ tb2,
               int B,
               const float* __restrict__ ew1, const float* __restrict__ eb1g) {
    extern __shared__ uint32_t smw[];
    float* smf = (float*)smw;
    const int tid = threadIdx.x;

    stage_btile(smw + IP_A, ew1, tid, 192);
    stage_btile(smw + IP_B, ew1 + 64 * 64, tid, 192);
    if (tid < 64) smf[IP_B1 + tid] = eb1g[tid];
    // compute tmean
    __shared__ float s1[64];
    if (tid < 64) {
        float w = tw1[tid], bb = tb1[tid];
        float acc = 0.f;
        for (int b = 0; b < B; b++) acc += silu(t[b] * w + bb);
        s1[tid] = acc / (float)B;
    }
    __syncthreads();
    if (tid < 64) {
        float o = tb2[tid];
        for (int k = 0; k < 64; k++) o += s1[k] * tw2[k * 64 + tid];
        smf[IP_TM + tid] = o;
    }
    __syncthreads();

    const int lane = tid & 31;
    const int wrp = tid >> 5;
    const int g = lane >> 2;
    const int t4 = lane & 3;
    uint32_t* Ah = smw + IP_WBASE + wrp * IP_WW;
    const float tm0 = smf[IP_TM + 2 * lane];
    const float tm1 = smf[IP_TM + 2 * lane + 1];

    const int gwarp = (blockIdx.x * 192 + tid) >> 5;
    const int nwarps = (gridDim.x * 192) >> 5;

    for (int grp = gwarp; grp < NODE_GROUPS; grp += nwarps) {
        const int base = grp * 32;
        const int zv = __ldg(&z[base + lane]);
        __syncwarp();
        #pragma unroll
        for (int e2 = 0; e2 < 32; e2++) {
            int nz = __shfl_sync(0xffffffffu, zv, e2);
            float2 ev = __ldg((const float2*)(emb + (size_t)nz * 64 + 2 * lane));
            float h0 = ev.x + tm0, h1 = ev.y + tm1;
            size_t idx = (size_t)(base + e2) * 64 + 2 * lane;
            *(float2*)(g_h + idx) = make_float2(h0, h1);
            *(float2*)(g_agg + idx) = make_float2(0.f, 0.f);
            Ah[e2 * 36 + lane] = f16_pack2(h0, h1);
        }
        __syncwarp();

        float accP[16][4], accQ[16][4];
        #pragma unroll
        for (int nt = 0; nt < 8; nt++) {
            float2 bb = *(const float2*)(smf + IP_B1 + 8 * nt + 2 * t4);
            #pragma unroll
            for (int mt = 0; mt < 2; mt++) {
                accP[mt * 8 + nt][0] = bb.x; accP[mt * 8 + nt][1] = bb.y;
                accP[mt * 8 + nt][2] = bb.x; accP[mt * 8 + nt][3] = bb.y;
                accQ[mt * 8 + nt][0] = 0.f; accQ[mt * 8 + nt][1] = 0.f;
                accQ[mt * 8 + nt][2] = 0.f; accQ[mt * 8 + nt][3] = 0.f;
            }
        }
        mma1_smem(accP, Ah, smw + IP_A, g, t4);
        mma1_smem(accQ, Ah, smw + IP_B, g, t4);
        #pragma unroll
        for (int mt = 0; mt < 2; mt++) {
            int r1 = base + 16 * mt + g;
            int r2 = r1 + 8;
            #pragma unroll
            for (int nt = 0; nt < 8; nt++) {
                int c = 8 * nt + 2 * t4;
                *(float2*)(g_P + (size_t)r1 * 64 + c) = make_float2(accP[mt * 8 + nt][0], accP[mt * 8 + nt][1]);
                *(float2*)(g_P + (size_t)r2 * 64 + c) = make_float2(accP[mt * 8 + nt][2], accP[mt * 8 + nt][3]);
                *(float2*)(g_Q + (size_t)r1 * 64 + c) = make_float2(accQ[mt * 8 + nt][0], accQ[mt * 8 + nt][1]);
                *(float2*)(g_Q + (size_t)r2 * 64 + c) = make_float2(accQ[mt * 8 + nt][2], accQ[mt * 8 + nt][3]);
            }
        }
    }
}

// ---------- edge kernel (fp16 1-term, 4 CTAs/SM) ----------
#define B_W2H  0
#define B_C1H  2304
#define SC_W1C 4608
#define SC_B2  4672
#define SC_CB1 4736
#define SC_CW2 4800
#define SC_CB2 4864
#define WARP_BASE 4868
#define WARP_W 1152
#define EDGE_SMEM_WORDS (WARP_BASE + 4 * WARP_W)
#define EDGE_SMEM_BYTES (EDGE_SMEM_WORDS * 4)   // 37,904 B -> 4 CTAs/SM

__global__ void __launch_bounds__(128, 4)
edge_kernel(const float* __restrict__ x, float* __restrict__ xn,
            const int* __restrict__ ei,
            const float* __restrict__ w1c_g,
            const float* __restrict__ ew2, const float* __restrict__ eb2g,
            const float* __restrict__ cw1, const float* __restrict__ cb1g,
            const float* __restrict__ cw2g, const float* __restrict__ cb2g,
            int do_agg) {
    extern __shared__ uint32_t smw[];
    float* smf = (float*)smw;
    const int tid = threadIdx.x;

    stage_btile(smw + B_W2H, ew2, tid, 128);
    stage_btile(smw + B_C1H, cw1, tid, 128);
    if (tid < 64) {
        smf[SC_W1C + tid] = w1c_g[tid];
        smf[SC_B2 + tid]  = eb2g[tid];
        smf[SC_CB1 + tid] = cb1g[tid];
        smf[SC_CW2 + tid] = cw2g[tid];
    }
    if (tid == 0) smf[SC_CB2] = cb2g[0];
    __syncthreads();

    const int lane = tid & 31;
    const int wrp = tid >> 5;
    const int g = lane >> 2;
    const int t = lane & 3;
    uint32_t* Ah = smw + WARP_BASE + wrp * WARP_W;
    const float w1c0 = smf[SC_W1C + 2 * lane];
    const float w1c1 = smf[SC_W1C + 2 * lane + 1];
    const float cb2s = smf[SC_CB2];

    const int gwarp = (blockIdx.x * 128 + tid) >> 5;
    const int nwarps = (gridDim.x * 128) >> 5;

    int grp = gwarp;
    int s_n = 0, d_n = 0;
    float xs0 = 0, xs1 = 0, xs2 = 0, xd0 = 0, xd1 = 0, xd2 = 0;
    if (grp < NGROUPS) {
        int e = grp * 32 + lane;
        s_n = ei[e]; d_n = ei[N_EDGES + e];
        xs0 = __ldg(&x[s_n * 3 + 0]); xs1 = __ldg(&x[s_n * 3 + 1]); xs2 = __ldg(&x[s_n * 3 + 2]);
        xd0 = __ldg(&x[d_n * 3 + 0]); xd1 = __ldg(&x[d_n * 3 + 1]); xd2 = __ldg(&x[d_n * 3 + 2]);
    }

    for (; grp < NGROUPS; grp += nwarps) {
        const int s = s_n, d = d_n;
        const float dx0 = xd0 - xs0;
        const float dx1 = xd1 - xs1;
        const float dx2 = xd2 - xs2;
        const float r2 = dx0 * dx0 + dx1 * dx1 + dx2 * dx2;

        // ---- prefetch next group FIRST: ei->x chain overlaps the gather below ----
        {
            int gn = grp + nwarps;
            if (gn < NGROUPS) {
                int e = gn * 32 + lane;
                s_n = ei[e]; d_n = ei[N_EDGES + e];
                xs0 = __ldg(&x[s_n * 3 + 0]); xs1 = __ldg(&x[s_n * 3 + 1]); xs2 = __ldg(&x[s_n * 3 + 2]);
                xd0 = __ldg(&x[d_n * 3 + 0]); xd1 = __ldg(&x[d_n * 3 + 1]); xd2 = __ldg(&x[d_n * 3 + 2]);
            }
        }

        // ---- gather + phase1 fused (indices via shfl); unroll 16 -> ~32 loads in flight ----
        __syncwarp();
        #pragma unroll 16
        for (int e2 = 0; e2 < 32; e2++) {
            int nd = __shfl_sync(0xffffffffu, d, e2);
            int ns = __shfl_sync(0xffffffffu, s, e2);
            float rr = __shfl_sync(0xffffffffu, r2, e2);
            float2 pv = __ldg((const float2*)(g_P + (size_t)nd * 64 + 2 * lane));
            float2 qv = __ldg((const float2*)(g_Q + (size_t)ns * 64 + 2 * lane));
            float f0 = silu(fmaf(rr, w1c0, pv.x + qv.x));
            float f1 = silu(fmaf(rr, w1c1, pv.y + qv.y));
            Ah[e2 * 36 + lane] = f16_pack2(f0, f1);
        }
        __syncwarp();

        // ---- matmul1: D = ef1 @ W2 + b2 ----
        float acc[16][4];
        #pragma unroll
        for (int nt = 0; nt < 8; nt++) {
            float2 bb = *(const float2*)(smf + SC_B2 + 8 * nt + 2 * t);
            #pragma unroll
            for (int mt = 0; mt < 2; mt++) {
                acc[mt * 8 + nt][0] = bb.x; acc[mt * 8 + nt][1] = bb.y;
                acc[mt * 8 + nt][2] = bb.x; acc[mt * 8 + nt][3] = bb.y;
            }
        }
        mma1_smem(acc, Ah, smw + B_W2H, g, t);

        // ---- m = silu(D); paired red.v4; pack to matmul2 A frags ----
        uint32_t mh[2][4][4];
        int dtop[2], dbot[2];
        #pragma unroll
        for (int mt = 0; mt < 2; mt++) {
            dtop[mt] = __shfl_sync(0xffffffffu, d, 16 * mt + g);
            dbot[mt] = __shfl_sync(0xffffffffu, d, 16 * mt + g + 8);
        }
        const int colbase_off = 2 * (t & ~1);
        #pragma unroll
        for (int mt = 0; mt < 2; mt++) {
            #pragma unroll
            for (int nt = 0; nt < 8; nt++) {
                float v0 = silu(acc[mt * 8 + nt][0]);
                float v1 = silu(acc[mt * 8 + nt][1]);
                float v2 = silu(acc[mt * 8 + nt][2]);
                float v3 = silu(acc[mt * 8 + nt][3]);
                if (do_agg) {
                    float px = (t & 1) ? v0 : v2;
                    float qx = (t & 1) ? v1 : v3;
                    float pr = __shfl_xor_sync(0xffffffffu, px, 1);
                    float qr = __shfl_xor_sync(0xffffffffu, qx, 1);
                    int row = (t & 1) ? dbot[mt] : dtop[mt];
                    int col = 8 * nt + colbase_off;
                    float a0 = (t & 1) ? pr : v0;
                    float a1 = (t & 1) ? qr : v1;
                    float a2 = (t & 1) ? v2 : pr;
                    float a3 = (t & 1) ? v3 : qr;
                    red_add_v4(&g_agg[(size_t)row * 64 + col], a0, a1, a2, a3);
                }
                int kt = nt >> 1, o = (nt & 1) * 2;
                mh[mt][kt][o]     = f16_pack2(v0, v1);
                mh[mt][kt][o + 1] = f16_pack2(v2, v3);
            }
        }

        // ---- matmul2: D2 = m @ C1 + cb1 ----
        float acc2[16][4];
        #pragma unroll
        for (int nt = 0; nt < 8; nt++) {
            float2 bb = *(const float2*)(smf + SC_CB1 + 8 * nt + 2 * t);
            #pragma unroll
            for (int mt = 0; mt < 2; mt++) {
                acc2[mt * 8 + nt][0] = bb.x; acc2[mt * 8 + nt][1] = bb.y;
                acc2[mt * 8 + nt][2] = bb.x; acc2[mt * 8 + nt][3] = bb.y;
            }
        }
        mma1_reg(acc2, mh, smw + B_C1H, g, t);

        // ---- coord epilogue ----
        float pr0 = 0.f, pr1 = 0.f, pr2 = 0.f, pr3 = 0.f;
        #pragma unroll
        for (int nt = 0; nt < 8; nt++) {
            float2 cwv = *(const float2*)(smf + SC_CW2 + 8 * nt + 2 * t);
            pr0 = fmaf(silu(acc2[nt][0]), cwv.x, pr0);
            pr0 = fmaf(silu(acc2[nt][1]), cwv.y, pr0);
            pr1 = fmaf(silu(acc2[nt][2]), cwv.x, pr1);
            pr1 = fmaf(silu(acc2[nt][3]), cwv.y, pr1);
            pr2 = fmaf(silu(acc2[8 + nt][0]), cwv.x, pr2);
            pr2 = fmaf(silu(acc2[8 + nt][1]), cwv.y, pr2);
            pr3 = fmaf(silu(acc2[8 + nt][2]), cwv.x, pr3);
            pr3 = fmaf(silu(acc2[8 + nt][3]), cwv.y, pr3);
        }
        pr0 += __shfl_xor_sync(0xffffffffu, pr0, 1);
        pr0 += __shfl_xor_sync(0xffffffffu, pr0, 2);
        pr1 += __shfl_xor_sync(0xffffffffu, pr1, 1);
        pr1 += __shfl_xor_sync(0xffffffffu, pr1, 2);
        pr2 += __shfl_xor_sync(0xffffffffu, pr2, 1);
        pr2 += __shfl_xor_sync(0xffffffffu, pr2, 2);
        pr3 += __shfl_xor_sync(0xffffffffu, pr3, 1);
        pr3 += __shfl_xor_sync(0xffffffffu, pr3, 2);
        float p = (t == 0) ? pr0 : (t == 1) ? pr1 : (t == 2) ? pr2 : pr3;
        const int e2l = g + 8 * t;
        p += cb2s;
        int dd = __shfl_sync(0xffffffffu, d, e2l);
        float ddx0 = __shfl_sync(0xffffffffu, dx0, e2l);
        float ddx1 = __shfl_sync(0xffffffffu, dx1, e2l);
        float ddx2 = __shfl_sync(0xffffffffu, dx2, e2l);
        atomicAdd(&xn[dd * 3 + 0], ddx0 * p);
        atomicAdd(&xn[dd * 3 + 1], ddx1 * p);
        atomicAdd(&xn[dd * 3 + 2], ddx2 * p);
    }
}

// ---------- node kernel (fp16 1-term) + fused next-layer P/Q ----------
#define N_W1H  0
#define N_W1A  2304
#define N_W2   4608
#define N_PA   6912
#define N_PB   9216
#define N_B1W  11520
#define N_B2W  11584
#define N_EB1W 11648
#define N_ABASE 11712
#define N_AW   1152
#define NODE_SMEM_WORDS (N_ABASE + 12 * N_AW)
#define NODE_SMEM_BYTES (NODE_SMEM_WORDS * 4)   // 102,144 B -> 1 CTA/SM at 384 thr

__global__ void __launch_bounds__(384)
node_kernel(const float* __restrict__ nw1, const float* __restrict__ nb1g,
            const float* __restrict__ nw2, const float* __restrict__ nb2g,
            const float* __restrict__ ew1n, const float* __restrict__ eb1n) {
    extern __shared__ uint32_t smw[];
    float* smf = (float*)smw;
    const int tid = threadIdx.x;

    stage_btile(smw + N_W1H, nw1, tid, 384);
    stage_btile(smw + N_W1A, nw1 + 64 * 64, tid, 384);
    stage_btile(smw + N_W2, nw2, tid, 384);
    stage_btile(smw + N_PA, ew1n, tid, 384);
    stage_btile(smw + N_PB, ew1n + 64 * 64, tid, 384);
    if (tid < 64) {
        smf[N_B1W + tid]  = nb1g[tid];
        smf[N_B2W + tid]  = nb2g[tid];
        smf[N_EB1W + tid] = eb1n[tid];
    }
    __syncthreads();

    const int lane = tid & 31;
    const int wrp = tid >> 5;
    const int g = lane >> 2;
    const int t = lane & 3;
    uint32_t* Ah = smw + N_ABASE + wrp * N_AW;

    const int gwarp = (blockIdx.x * 384 + tid) >> 5;
    const int nwarps = (gridDim.x * 384) >> 5;

    for (int grp = gwarp; grp < NODE_GROUPS; grp += nwarps) {
        const int base = grp * 32;

        __syncwarp();
        #pragma unroll
        for (int e2 = 0; e2 < 32; e2++) {
            float2 hv = __ldg((const float2*)(g_h + (size_t)(base + e2) * 64 + 2 * lane));
            Ah[e2 * 36 + lane] = f16_pack2(hv.x, hv.y);
        }
        __syncwarp();

        float acc1[16][4];
        #pragma unroll
        for (int nt = 0; nt < 8; nt++) {
            float2 bb = *(const float2*)(smf + N_B1W + 8 * nt + 2 * t);
            #pragma unroll
            for (int mt = 0; mt < 2; mt++) {
                acc1[mt * 8 + nt][0] = bb.x; acc1[mt * 8 + nt][1] = bb.y;
                acc1[mt * 8 + nt][2] = bb.x; acc1[mt * 8 + nt][3] = bb.y;
            }
        }
        mma1_smem(acc1, Ah, smw + N_W1H, g, t);

        __syncwarp();
        #pragma unroll
        for (int e2 = 0; e2 < 32; e2++) {
            float2* ap = (float2*)(g_agg + (size_t)(base + e2) * 64 + 2 * lane);
            float2 av = *ap;
            *ap = make_float2(0.f, 0.f);
            Ah[e2 * 36 + lane] = f16_pack2(av.x, av.y);
        }
        __syncwarp();
        mma1_smem(acc1, Ah, smw + N_W1A, g, t);

        uint32_t mh[2][4][4];
        #pragma unroll
        for (int mt = 0; mt < 2; mt++) {
            #pragma unroll
            for (int nt = 0; nt < 8; nt++) {
                float v0 = silu(acc1[mt * 8 + nt][0]);
                float v1 = silu(acc1[mt * 8 + nt][1]);
                float v2 = silu(acc1[mt * 8 + nt][2]);
                float v3 = silu(acc1[mt * 8 + nt][3]);
                int kt = nt >> 1, o = (nt & 1) * 2;
                mh[mt][kt][o]     = f16_pack2(v0, v1);
                mh[mt][kt][o + 1] = f16_pack2(v2, v3);
            }
        }

        float acc2[16][4];
        #pragma unroll
        for (int nt = 0; nt < 8; nt++) {
            float2 bb = *(const float2*)(smf + N_B2W + 8 * nt + 2 * t);
            #pragma unroll
            for (int mt = 0; mt < 2; mt++) {
                acc2[mt * 8 + nt][0] = bb.x; acc2[mt * 8 + nt][1] = bb.y;
                acc2[mt * 8 + nt][2] = bb.x; acc2[mt * 8 + nt][3] = bb.y;
            }
        }
        mma1_reg(acc2, mh, smw + N_W2, g, t);

        uint32_t hh[2][4][4];
        #pragma unroll
        for (int mt = 0; mt < 2; mt++) {
            int r1 = base + 16 * mt + g;
            int r2 = r1 + 8;
            #pragma unroll
            for (int nt = 0; nt < 8; nt++) {
                int c = 8 * nt + 2 * t;
                float2 h1 = __ldg((const float2*)(g_h + (size_t)r1 * 64 + c));
                float2 h2 = __ldg((const float2*)(g_h + (size_t)r2 * 64 + c));
                float v0 = h1.x + acc2[mt * 8 + nt][0];
                float v1 = h1.y + acc2[mt * 8 + nt][1];
                float v2 = h2.x + acc2[mt * 8 + nt][2];
                float v3 = h2.y + acc2[mt * 8 + nt][3];
                *(float2*)(g_h + (size_t)r1 * 64 + c) = make_float2(v0, v1);
                *(float2*)(g_h + (size_t)r2 * 64 + c) = make_float2(v2, v3);
                int kt = nt >> 1, o = (nt & 1) * 2;
                hh[mt][kt][o]     = f16_pack2(v0, v1);
                hh[mt][kt][o + 1] = f16_pack2(v2, v3);
            }
        }

        float accp[16][4];
        #pragma unroll
        for (int nt = 0; nt < 8; nt++) {
            float2 bb = *(const float2*)(smf + N_EB1W + 8 * nt + 2 * t);
            #pragma unroll
            for (int mt = 0; mt < 2; mt++) {
                accp[mt * 8 + nt][0] = bb.x; accp[mt * 8 + nt][1] = bb.y;
                accp[mt * 8 + nt][2] = bb.x; accp[mt * 8 + nt][3] = bb.y;
            }
        }
        mma1_reg(accp, hh, smw + N_PA, g, t);
        #pragma unroll
        for (int mt = 0; mt < 2; mt++) {
            int r1 = base + 16 * mt + g;
            int r2 = r1 + 8;
            #pragma unroll
            for (int nt = 0; nt < 8; nt++) {
                int c = 8 * nt + 2 * t;
                *(float2*)(g_P + (size_t)r1 * 64 + c) = make_float2(accp[mt * 8 + nt][0], accp[mt * 8 + nt][1]);
                *(float2*)(g_P + (size_t)r2 * 64 + c) = make_float2(accp[mt * 8 + nt][2], accp[mt * 8 + nt][3]);
            }
        }

        #pragma unroll
        for (int a = 0; a < 16; a++) {
            accp[a][0] = 0.f; accp[a][1] = 0.f; accp[a][2] = 0.f; accp[a][3] = 0.f;
        }
        mma1_reg(accp, hh, smw + N_PB, g, t);
        #pragma unroll
        for (int mt = 0; mt < 2; mt++) {
            int r1 = base + 16 * mt + g;
            int r2 = r1 + 8;
            #pragma unroll
            for (int nt = 0; nt < 8; nt++) {
                int c = 8 * nt + 2 * t;
                *(float2*)(g_Q + (size_t)r1 * 64 + c) = make_float2(accp[mt * 8 + nt][0], accp[mt * 8 + nt][1]);
                *(float2*)(g_Q + (size_t)r2 * 64 + c) = make_float2(accp[mt * 8 + nt][2], accp[mt * 8 + nt][3]);
            }
        }
    }
}

// ---------- launch ----------
extern "C" void kernel_launch(void* const* d_in, const int* in_sizes, int n_in,
                              void* d_out, int out_size) {
    const float* x   = (const float*)d_in[0];
    const int*   z   = (const int*)d_in[1];
    const float* t   = (const float*)d_in[2];
    const int*   ei  = (const int*)d_in[3];
    const float* emb = (const float*)d_in[4];
    const float* tw1 = (const float*)d_in[5];
    const float* tb1 = (const float*)d_in[6];
    const float* tw2 = (const float*)d_in[7];
    const float* tb2 = (const float*)d_in[8];
    const float* ew1 = (const float*)d_in[9];
    const float* eb1 = (const float*)d_in[10];
    const float* ew2 = (const float*)d_in[11];
    const float* eb2 = (const float*)d_in[12];
    const float* cw1 = (const float*)d_in[13];
    const float* cb1 = (const float*)d_in[14];
    const float* cw2 = (const float*)d_in[15];
    const float* cb2 = (const float*)d_in[16];
    const float* nw1 = (const float*)d_in[17];
    const float* nb1 = (const float*)d_in[18];
    const float* nw2 = (const float*)d_in[19];
    const float* nb2 = (const float*)d_in[20];
    float* out = (float*)d_out;
    const int B = in_sizes[2];

    float *pxA, *pxB;
    cudaGetSymbolAddress((void**)&pxA, g_xA);
    cudaGetSymbolAddress((void**)&pxB, g_xB);

    cudaFuncSetAttribute(edge_kernel, cudaFuncAttributeMaxDynamicSharedMemorySize, EDGE_SMEM_BYTES);
    cudaFuncSetAttribute(node_kernel, cudaFuncAttributeMaxDynamicSharedMemorySize, NODE_SMEM_BYTES);
    cudaFuncSetAttribute(initpre_kernel, cudaFuncAttributeMaxDynamicSharedMemorySize, IP_SMEM_BYTES);

    const size_t XB = (size_t)N_NODES * 3 * sizeof(float);
    const int EGRID = 608;   // 4 CTAs/SM x 152

    initpre_kernel<<<304, 192, IP_SMEM_BYTES>>>(z, emb, t, tw1, tb1, tw2, tb2, B,
                                                ew1 + 0 * 129 * 64, eb1 + 0 * 64);

    // ---- layer 0 ----
    cudaMemcpyAsync(pxB, x, XB, cudaMemcpyDeviceToDevice, 0);
    edge_kernel<<<EGRID, 128, EDGE_SMEM_BYTES>>>(x, pxB, ei,
        ew1 + 0 * 129 * 64 + 128 * 64, ew2 + 0 * 4096, eb2 + 0 * 64,
        cw1 + 0 * 4096, cb1 + 0 * 64, cw2 + 0 * 64, cb2 + 0, 1);
    node_kernel<<<152, 384, NODE_SMEM_BYTES>>>(nw1 + 0 * 128 * 64, nb1 + 0 * 64,
                                               nw2 + 0 * 4096, nb2 + 0 * 64,
                                               ew1 + 1 * 129 * 64, eb1 + 1 * 64);

    // ---- layer 1 ----
    cudaMemcpyAsync(pxA, pxB, XB, cudaMemcpyDeviceToDevice, 0);
    edge_kernel<<<EGRID, 128, EDGE_SMEM_BYTES>>>(pxB, pxA, ei,
        ew1 + 1 * 129 * 64 + 128 * 64, ew2 + 1 * 4096, eb2 + 1 * 64,
        cw1 + 1 * 4096, cb1 + 1 * 64, cw2 + 1 * 64, cb2 + 1, 1);
    node_kernel<<<152, 384, NODE_SMEM_BYTES>>>(nw1 + 1 * 128 * 64, nb1 + 1 * 64,
                                               nw2 + 1 * 4096, nb2 + 1 * 64,
                                               ew1 + 2 * 129 * 64, eb1 + 2 * 64);

    // ---- layer 2: agg/node dead, write x' straight to d_out ----
    cudaMemcpyAsync(out, pxA, XB, cudaMemcpyDeviceToDevice, 0);
    edge_kernel<<<EGRID, 128, EDGE_SMEM_BYTES>>>(pxA, out, ei,
        ew1 + 2 * 129 * 64 + 128 * 64, ew2 + 2 * 4096, eb2 + 2 * 64,
        cw1 + 2 * 4096, cb1 + 2 * 64, cw2 + 2 * 64, cb2 + 2, 0);
}